// round 1
// baseline (speedup 1.0000x reference)
#include <cuda_runtime.h>
#include <cuda_bf16.h>

// Problem dims
#define BATCH 256
#define CIN   2048
#define LL    150
#define CC    256
#define H1    8192
#define OUTN  2048

// Scratch (device globals; no dynamic allocation allowed)
__device__ float g_pv [BATCH * CC * LL];    // value projection  [B][C][L]
__device__ float g_q  [BATCH * CC * LL];    // query (reused as att-out scratch)
__device__ float g_k  [BATCH * CC * LL];    // key
__device__ float g_att[BATCH * LL * LL];    // energy / softmax  [B][L][L]
__device__ float g_out[BATCH * CC * LL];    // gamma*attout + pv
__device__ float g_h  [BATCH * H1];         // fc1 activations

// ---------------------------------------------------------------------------
// Generic tiled SGEMM: C[M,N] = op(A) * op(B) (+ bias)
//   TA=0: A is [M,K] row-major (lda = row stride). TA=1: A is [K,M], use A[k,m].
//   TB=0: B is [K,N] row-major.                    TB=1: B is [N,K], use B[n,k].
//   BIASM: 0 none, 1 bias[m], 2 bias[n]
// Batched via blockIdx.z with element strides sA/sB/sC (0 = shared operand).
// BM=128, BN=64, BK=16, 256 threads, each computes 8x4.
// ---------------------------------------------------------------------------
#define BM 128
#define BN 64
#define BK 16
#define TM 8
#define TN 4

template<int TA, int TB, int BIASM>
__global__ __launch_bounds__(256)
void sgemm_kernel(const float* __restrict__ A, const float* __restrict__ B,
                  const float* __restrict__ bias, float* __restrict__ C,
                  int M, int N, int K, int lda, int ldb, int ldc,
                  long long sA, long long sB, long long sC)
{
    A += (long long)blockIdx.z * sA;
    B += (long long)blockIdx.z * sB;
    C += (long long)blockIdx.z * sC;

    const int tid = threadIdx.x;
    const int tx = tid & 15;   // n direction (16 * TN = 64)
    const int ty = tid >> 4;   // m direction (16 * TM = 128)
    const int m0 = blockIdx.y * BM;
    const int n0 = blockIdx.x * BN;

    __shared__ float As[BK][BM];
    __shared__ float Bs[BK][BN];

    float acc[TM][TN];
#pragma unroll
    for (int i = 0; i < TM; i++)
#pragma unroll
        for (int j = 0; j < TN; j++) acc[i][j] = 0.f;

    for (int k0 = 0; k0 < K; k0 += BK) {
        // ---- load A tile (BM x BK) into As[k][m] ----
        if (TA == 0) {
            int m  = tid >> 1;          // 0..127
            int kb = (tid & 1) * 8;     // 0 or 8
            int gm = m0 + m;
#pragma unroll
            for (int j = 0; j < 8; j++) {
                int gk = k0 + kb + j;
                As[kb + j][m] = (gm < M && gk < K)
                    ? A[(long long)gm * lda + gk] : 0.f;
            }
        } else {
            int kk = tid >> 4;          // 0..15
            int mb = (tid & 15) * 8;
            int gk = k0 + kk;
#pragma unroll
            for (int j = 0; j < 8; j++) {
                int gm = m0 + mb + j;
                As[kk][mb + j] = (gm < M && gk < K)
                    ? A[(long long)gk * lda + gm] : 0.f;
            }
        }
        // ---- load B tile (BK x BN) into Bs[k][n] ----
        if (TB == 0) {
            int kk = tid >> 4;          // 0..15
            int nb = (tid & 15) * 4;
            int gk = k0 + kk;
#pragma unroll
            for (int j = 0; j < 4; j++) {
                int gn = n0 + nb + j;
                Bs[kk][nb + j] = (gk < K && gn < N)
                    ? B[(long long)gk * ldb + gn] : 0.f;
            }
        } else {
            int n  = tid >> 2;          // 0..63
            int kb = (tid & 3) * 4;
            int gn = n0 + n;
#pragma unroll
            for (int j = 0; j < 4; j++) {
                int gk = k0 + kb + j;
                Bs[kb + j][n] = (gn < N && gk < K)
                    ? B[(long long)gn * ldb + gk] : 0.f;
            }
        }
        __syncthreads();

#pragma unroll
        for (int kk = 0; kk < BK; kk++) {
            float a[TM], b[TN];
#pragma unroll
            for (int i = 0; i < TM; i++) a[i] = As[kk][ty * TM + i];
#pragma unroll
            for (int j = 0; j < TN; j++) b[j] = Bs[kk][tx * TN + j];
#pragma unroll
            for (int i = 0; i < TM; i++)
#pragma unroll
                for (int j = 0; j < TN; j++)
                    acc[i][j] = fmaf(a[i], b[j], acc[i][j]);
        }
        __syncthreads();
    }

    // ---- epilogue ----
#pragma unroll
    for (int i = 0; i < TM; i++) {
        int gm = m0 + ty * TM + i;
        if (gm >= M) continue;
#pragma unroll
        for (int j = 0; j < TN; j++) {
            int gn = n0 + tx * TN + j;
            if (gn >= N) continue;
            float v = acc[i][j];
            if (BIASM == 1) v += bias[gm];
            if (BIASM == 2) v += bias[gn];
            C[(long long)gm * ldc + gn] = v;
        }
    }
}

// ---------------------------------------------------------------------------
// Softmax over rows of length n (n <= 160): one warp per row.
// ---------------------------------------------------------------------------
__global__ void softmax_rows_kernel(float* __restrict__ att, int rows, int n)
{
    int warp = (blockIdx.x * blockDim.x + threadIdx.x) >> 5;
    int lane = threadIdx.x & 31;
    if (warp >= rows) return;
    float* row = att + (long long)warp * n;

    float vals[5];
    float mx = -1e30f;
#pragma unroll
    for (int i = 0; i < 5; i++) {
        int c = lane + 32 * i;
        vals[i] = (c < n) ? row[c] : -1e30f;
        mx = fmaxf(mx, vals[i]);
    }
#pragma unroll
    for (int o = 16; o; o >>= 1) mx = fmaxf(mx, __shfl_xor_sync(0xffffffffu, mx, o));

    float s = 0.f;
#pragma unroll
    for (int i = 0; i < 5; i++) {
        vals[i] = expf(vals[i] - mx);   // padded lanes: exp(-inf) = 0
        s += vals[i];
    }
#pragma unroll
    for (int o = 16; o; o >>= 1) s += __shfl_xor_sync(0xffffffffu, s, o);
    float inv = 1.f / s;
#pragma unroll
    for (int i = 0; i < 5; i++) {
        int c = lane + 32 * i;
        if (c < n) row[c] = vals[i] * inv;
    }
}

// out = gamma[0] * a + pv   (elementwise)
__global__ void residual_kernel(const float* __restrict__ gamma,
                                const float* __restrict__ a,
                                const float* __restrict__ pv,
                                float* __restrict__ out, int n)
{
    int i = blockIdx.x * blockDim.x + threadIdx.x;
    if (i < n) out[i] = gamma[0] * a[i] + pv[i];
}

static inline int ceil_div(int a, int b) { return (a + b - 1) / b; }

extern "C" void kernel_launch(void* const* d_in, const int* in_sizes, int n_in,
                              void* d_out, int out_size)
{
    const float* x     = (const float*)d_in[0];   // [B, CIN, L, 1]
    const float* Wv    = (const float*)d_in[1];   // [C, CIN]
    const float* bv    = (const float*)d_in[2];
    const float* Wq    = (const float*)d_in[3];   // [C, C]
    const float* bq    = (const float*)d_in[4];
    const float* Wk    = (const float*)d_in[5];
    const float* bk    = (const float*)d_in[6];
    const float* gamma = (const float*)d_in[7];
    const float* W1    = (const float*)d_in[8];   // [H1, C*L]
    const float* b1    = (const float*)d_in[9];
    const float* W2    = (const float*)d_in[10];  // [OUT, H1]
    const float* b2    = (const float*)d_in[11];
    float* out = (float*)d_out;

    float *pv, *q, *k, *att, *aout, *h;
    cudaGetSymbolAddress((void**)&pv,  g_pv);
    cudaGetSymbolAddress((void**)&q,   g_q);
    cudaGetSymbolAddress((void**)&k,   g_k);
    cudaGetSymbolAddress((void**)&att, g_att);
    cudaGetSymbolAddress((void**)&aout,g_out);
    cudaGetSymbolAddress((void**)&h,   g_h);

    const long long sX  = (long long)CIN * LL;   // 307200
    const long long sPV = (long long)CC * LL;    // 38400
    const long long sAT = (long long)LL * LL;    // 22500

    // 1) pv[b] = Wv[C,CIN] * x[b][CIN,L] + bv    (bias per M row)
    {
        dim3 grid(ceil_div(LL, BN), ceil_div(CC, BM), BATCH);
        sgemm_kernel<0,0,1><<<grid, 256>>>(Wv, x, bv, pv,
            CC, LL, CIN, CIN, LL, LL, 0, sX, sPV);
    }
    // 2) q[b] = Wq * pv[b] + bq ;  3) k[b] = Wk * pv[b] + bk
    {
        dim3 grid(ceil_div(LL, BN), ceil_div(CC, BM), BATCH);
        sgemm_kernel<0,0,1><<<grid, 256>>>(Wq, pv, bq, q,
            CC, LL, CC, CC, LL, LL, 0, sPV, sPV);
        sgemm_kernel<0,0,1><<<grid, 256>>>(Wk, pv, bk, k,
            CC, LL, CC, CC, LL, LL, 0, sPV, sPV);
    }
    // 4) energy[b][L,L] = q[b]^T * k[b]   (TA=1)
    {
        dim3 grid(ceil_div(LL, BN), ceil_div(LL, BM), BATCH);
        sgemm_kernel<1,0,0><<<grid, 256>>>(q, k, nullptr, att,
            LL, LL, CC, LL, LL, LL, sPV, sPV, sAT);
    }
    // 5) softmax rows
    {
        int rows = BATCH * LL;                       // 38400 rows
        int blocks = ceil_div(rows * 32, 256);
        softmax_rows_kernel<<<blocks, 256>>>(att, rows, LL);
    }
    // 6) attout[b][C,L] = pv[b] * att[b]^T  (TB=1) -> reuse q as scratch
    {
        dim3 grid(ceil_div(LL, BN), ceil_div(CC, BM), BATCH);
        sgemm_kernel<0,1,0><<<grid, 256>>>(pv, att, nullptr, q,
            CC, LL, LL, LL, LL, LL, sPV, sAT, sPV);
    }
    // 7) out = gamma * attout + pv
    {
        int n = BATCH * CC * LL;
        residual_kernel<<<ceil_div(n, 256), 256>>>(gamma, q, pv, aout, n);
    }
    // 8) fc1: h[B,H1] = out_flat[B, C*L] * W1^T + b1   (TB=1, bias per N)
    {
        dim3 grid(ceil_div(H1, BN), ceil_div(BATCH, BM), 1);
        sgemm_kernel<0,1,2><<<grid, 256>>>(aout, W1, b1, h,
            BATCH, H1, CC * LL, CC * LL, CC * LL, H1, 0, 0, 0);
    }
    // 9) fc2: out[B,OUT] = h * W2^T + b2
    {
        dim3 grid(ceil_div(OUTN, BN), ceil_div(BATCH, BM), 1);
        sgemm_kernel<0,1,2><<<grid, 256>>>(h, W2, b2, out,
            BATCH, OUTN, H1, H1, H1, OUTN, 0, 0, 0);
    }
}

// round 4
// speedup vs baseline: 1.5476x; 1.5476x over previous
#include <cuda_runtime.h>
#include <cuda_bf16.h>
#include <cstdint>

// Problem dims
#define BATCH 256
#define CIN   2048
#define LL    150
#define CC    256
#define H1    8192
#define OUTN  2048

// Scratch (device globals; no dynamic allocation allowed)
__device__ __align__(16) float g_pv [BATCH * CC * LL];
__device__ __align__(16) float g_q  [BATCH * CC * LL];
__device__ __align__(16) float g_k  [BATCH * CC * LL];
__device__ __align__(16) float g_att[BATCH * LL * LL];
__device__ __align__(16) float g_out[BATCH * CC * LL];
__device__ __align__(16) float g_h  [BATCH * H1];
__device__ __align__(16) float g_xT [BATCH * LL * CIN];

// ===========================================================================
// Warp-level bf16 MMA helpers (family-portable PTX: valid on plain sm_103)
// ===========================================================================
__device__ __forceinline__ uint32_t smem_u32(const void* p) {
    uint32_t a;
    asm("{ .reg .u64 t; cvta.to.shared.u64 t, %1; cvt.u32.u64 %0, t; }"
        : "=r"(a) : "l"(p));
    return a;
}
__device__ __forceinline__ void ldsm4(uint32_t& r0, uint32_t& r1, uint32_t& r2,
                                      uint32_t& r3, uint32_t addr) {
    asm volatile("ldmatrix.sync.aligned.m8n8.x4.shared.b16 {%0,%1,%2,%3}, [%4];"
                 : "=r"(r0), "=r"(r1), "=r"(r2), "=r"(r3) : "r"(addr));
}
__device__ __forceinline__ void mma_bf16(float* c, const uint32_t* a,
                                         const uint32_t* b) {
    asm volatile(
        "mma.sync.aligned.m16n8k16.row.col.f32.bf16.bf16.f32 "
        "{%0,%1,%2,%3}, {%4,%5,%6,%7}, {%8,%9}, {%0,%1,%2,%3};"
        : "+f"(c[0]), "+f"(c[1]), "+f"(c[2]), "+f"(c[3])
        : "r"(a[0]), "r"(a[1]), "r"(a[2]), "r"(a[3]), "r"(b[0]), "r"(b[1]));
}

// ===========================================================================
// Split-bf16 tensor-core GEMM: C[M,N] = A[M,K] * B[N,K]^T (+ epilogue)
// A, B fp32 K-major. hi = trunc-to-bf16, lo = rn(x - hi); 3 MMA passes:
// Ahi*Bhi + Ahi*Blo + Alo*Bhi  (fp32-like precision).
// Tile 128x128, BK=32, 256 threads (8 warps, warp tile 64x32).
// EPI: 0 none, 1 +bias[m], 2 +bias[n], 3 gamma[0]*acc + res[]
// Batched via blockIdx.z with strides sA/sB/sC (res uses sC too).
// ===========================================================================
#define RS 40   // SMEM row stride in bf16 elements (80B = 5*16B, ldmatrix-safe)

// load 128 rows x 32 k of fp32, convert to hi/lo bf16, store to SMEM
__device__ __forceinline__ void load_conv(const float* __restrict__ G, int rows,
        int Kdim, int ld, int row0, int k0,
        __nv_bfloat16* hiS, __nv_bfloat16* loS, int tid, bool vecok)
{
    int r = tid >> 1;
    int cbase = (tid & 1) * 16;
    int gr = row0 + r;
    const float* Grow = G + (long long)gr * ld;
    bool rok = gr < rows;
#pragma unroll
    for (int i = 0; i < 4; i++) {
        int gk = k0 + cbase + i * 4;
        float4 v = make_float4(0.f, 0.f, 0.f, 0.f);
        if (rok) {
            if (vecok && gk + 3 < Kdim) {
                v = *reinterpret_cast<const float4*>(Grow + gk);
            } else {
                if (gk     < Kdim) v.x = Grow[gk];
                if (gk + 1 < Kdim) v.y = Grow[gk + 1];
                if (gk + 2 < Kdim) v.z = Grow[gk + 2];
                if (gk + 3 < Kdim) v.w = Grow[gk + 3];
            }
        }
        uint32_t b0 = __float_as_uint(v.x), b1 = __float_as_uint(v.y);
        uint32_t b2 = __float_as_uint(v.z), b3 = __float_as_uint(v.w);
        uint32_t hi01 = (b1 & 0xFFFF0000u) | (b0 >> 16);
        uint32_t hi23 = (b3 & 0xFFFF0000u) | (b2 >> 16);
        float l0 = v.x - __uint_as_float(b0 & 0xFFFF0000u);
        float l1 = v.y - __uint_as_float(b1 & 0xFFFF0000u);
        float l2 = v.z - __uint_as_float(b2 & 0xFFFF0000u);
        float l3 = v.w - __uint_as_float(b3 & 0xFFFF0000u);
        uint32_t lo01, lo23;
        asm("cvt.rn.bf16x2.f32 %0, %1, %2;" : "=r"(lo01) : "f"(l1), "f"(l0));
        asm("cvt.rn.bf16x2.f32 %0, %1, %2;" : "=r"(lo23) : "f"(l3), "f"(l2));
        int e = r * RS + cbase + i * 4;
        *reinterpret_cast<uint2*>(hiS + e) = make_uint2(hi01, hi23);
        *reinterpret_cast<uint2*>(loS + e) = make_uint2(lo01, lo23);
    }
}

template<int EPI>
__global__ __launch_bounds__(256)
void mma_gemm(const float* __restrict__ A, const float* __restrict__ B,
              const float* __restrict__ bias, const float* __restrict__ gamma,
              const float* __restrict__ res, float* __restrict__ C,
              int M, int N, int K, int lda, int ldb, int ldc,
              long long sA, long long sB, long long sC)
{
    __shared__ __nv_bfloat16 AsHi[128 * RS], AsLo[128 * RS];
    __shared__ __nv_bfloat16 BsHi[128 * RS], BsLo[128 * RS];

    A += (long long)blockIdx.z * sA;
    B += (long long)blockIdx.z * sB;
    C += (long long)blockIdx.z * sC;
    if (EPI == 3) res += (long long)blockIdx.z * sC;

    const int tid  = threadIdx.x;
    const int wid  = tid >> 5;
    const int lane = tid & 31;
    const int wm = wid >> 2;          // 0..1 -> m offset *64
    const int wn = wid & 3;           // 0..3 -> n offset *32
    const int m0 = blockIdx.y * 128;
    const int n0 = blockIdx.x * 128;

    const bool vA = ((lda & 3) == 0);
    const bool vB = ((ldb & 3) == 0);

    const uint32_t aHi = smem_u32(AsHi), aLo = smem_u32(AsLo);
    const uint32_t bHi = smem_u32(BsHi), bLo = smem_u32(BsLo);

    // per-lane ldmatrix source coordinates
    const int q = lane >> 3, r8 = lane & 7;
    const int a_row  = wm * 64 + ((q & 1) << 3) + r8;   // + mi*16
    const int a_koff = (q >> 1) << 3;                   // + ks*16
    const int b_row  = wn * 32 + ((q >> 1) << 3) + r8;  // + nb*16
    const int b_koff = (q & 1) << 3;                    // + ks*16

    float acc[4][4][4];
#pragma unroll
    for (int mi = 0; mi < 4; mi++)
#pragma unroll
        for (int ni = 0; ni < 4; ni++)
#pragma unroll
            for (int v = 0; v < 4; v++) acc[mi][ni][v] = 0.f;

    const int nch = (K + 31) >> 5;
    for (int ch = 0; ch < nch; ch++) {
        int k0 = ch * 32;
        load_conv(A, M, K, lda, m0, k0, AsHi, AsLo, tid, vA);
        load_conv(B, N, K, ldb, n0, k0, BsHi, BsLo, tid, vB);
        __syncthreads();

#pragma unroll
        for (int pass = 0; pass < 3; pass++) {
            uint32_t Ab = (pass == 2) ? aLo : aHi;
            uint32_t Bb = (pass == 1) ? bLo : bHi;
#pragma unroll
            for (int ks = 0; ks < 2; ks++) {
                uint32_t af[4][4];
#pragma unroll
                for (int mi = 0; mi < 4; mi++) {
                    uint32_t ad = Ab + (uint32_t)(((a_row + mi * 16) * RS
                                    + ks * 16 + a_koff) * 2);
                    ldsm4(af[mi][0], af[mi][1], af[mi][2], af[mi][3], ad);
                }
                uint32_t bf[4][2];
#pragma unroll
                for (int nb = 0; nb < 2; nb++) {
                    uint32_t bd = Bb + (uint32_t)(((b_row + nb * 16) * RS
                                    + ks * 16 + b_koff) * 2);
                    uint32_t t0, t1, t2, t3;
                    ldsm4(t0, t1, t2, t3, bd);
                    bf[nb * 2][0] = t0; bf[nb * 2][1] = t1;
                    bf[nb * 2 + 1][0] = t2; bf[nb * 2 + 1][1] = t3;
                }
#pragma unroll
                for (int mi = 0; mi < 4; mi++)
#pragma unroll
                    for (int ni = 0; ni < 4; ni++)
                        mma_bf16(acc[mi][ni], af[mi], bf[ni]);
            }
        }
        __syncthreads();
    }

    // epilogue
    const float gm_s = (EPI == 3) ? gamma[0] : 0.f;
#pragma unroll
    for (int mi = 0; mi < 4; mi++) {
        int gm0 = m0 + wm * 64 + mi * 16 + (lane >> 2);
#pragma unroll
        for (int half = 0; half < 2; half++) {
            int gm = gm0 + half * 8;
            if (gm >= M) continue;
            float bm = (EPI == 1) ? bias[gm] : 0.f;
#pragma unroll
            for (int ni = 0; ni < 4; ni++) {
                int gn = n0 + wn * 32 + ni * 8 + 2 * (lane & 3);
                if (gn >= N) continue;
                float v0 = acc[mi][ni][half * 2];
                float v1 = acc[mi][ni][half * 2 + 1];
                long long idx = (long long)gm * ldc + gn;
                if (EPI == 1) { v0 += bm; v1 += bm; }
                if (EPI == 2) { v0 += bias[gn]; v1 += (gn + 1 < N) ? bias[gn + 1] : 0.f; }
                if (EPI == 3) {
                    v0 = gm_s * v0 + res[idx];
                    if (gn + 1 < N) v1 = gm_s * v1 + res[idx + 1];
                }
                if (gn + 1 < N) {
                    *reinterpret_cast<float2*>(C + idx) = make_float2(v0, v1);
                } else {
                    C[idx] = v0;
                }
            }
        }
    }
}

// ===========================================================================
// x transpose: [B][CIN][L] -> [B][L][CIN]
// ===========================================================================
__global__ void transpose_x_kernel(const float* __restrict__ x, float* __restrict__ xT)
{
    __shared__ float t[32][33];
    int b  = blockIdx.z;
    int c0 = blockIdx.y * 32, l0 = blockIdx.x * 32;
    const float* xb = x + (long long)b * CIN * LL;
    float* xTb = xT + (long long)b * LL * CIN;
    int tx = threadIdx.x, ty = threadIdx.y;
#pragma unroll
    for (int i = ty; i < 32; i += 8) {
        int c = c0 + i, l = l0 + tx;
        t[i][tx] = (c < CIN && l < LL) ? xb[(long long)c * LL + l] : 0.f;
    }
    __syncthreads();
#pragma unroll
    for (int i = ty; i < 32; i += 8) {
        int l = l0 + i, c = c0 + tx;
        if (l < LL && c < CIN) xTb[(long long)l * CIN + c] = t[tx][i];
    }
}

// ===========================================================================
// SIMT SGEMM for the small attention GEMMs (q, k, energy)
// ===========================================================================
#define BM 128
#define BN 64
#define BK 16
#define TM 8
#define TN 4

template<int TA, int TB, int BIASM>
__global__ __launch_bounds__(256)
void sgemm_kernel(const float* __restrict__ A, const float* __restrict__ B,
                  const float* __restrict__ bias, float* __restrict__ C,
                  int M, int N, int K, int lda, int ldb, int ldc,
                  long long sA, long long sB, long long sC)
{
    A += (long long)blockIdx.z * sA;
    B += (long long)blockIdx.z * sB;
    C += (long long)blockIdx.z * sC;

    const int tid = threadIdx.x;
    const int tx = tid & 15;
    const int ty = tid >> 4;
    const int m0 = blockIdx.y * BM;
    const int n0 = blockIdx.x * BN;

    __shared__ float As[BK][BM];
    __shared__ float Bs[BK][BN];

    float acc[TM][TN];
#pragma unroll
    for (int i = 0; i < TM; i++)
#pragma unroll
        for (int j = 0; j < TN; j++) acc[i][j] = 0.f;

    for (int k0 = 0; k0 < K; k0 += BK) {
        if (TA == 0) {
            int m  = tid >> 1;
            int kb = (tid & 1) * 8;
            int gm = m0 + m;
#pragma unroll
            for (int j = 0; j < 8; j++) {
                int gk = k0 + kb + j;
                As[kb + j][m] = (gm < M && gk < K) ? A[(long long)gm * lda + gk] : 0.f;
            }
        } else {
            int kk = tid >> 4;
            int mb = (tid & 15) * 8;
            int gk = k0 + kk;
#pragma unroll
            for (int j = 0; j < 8; j++) {
                int gm = m0 + mb + j;
                As[kk][mb + j] = (gm < M && gk < K) ? A[(long long)gk * lda + gm] : 0.f;
            }
        }
        if (TB == 0) {
            int kk = tid >> 4;
            int nb = (tid & 15) * 4;
            int gk = k0 + kk;
#pragma unroll
            for (int j = 0; j < 4; j++) {
                int gn = n0 + nb + j;
                Bs[kk][nb + j] = (gk < K && gn < N) ? B[(long long)gk * ldb + gn] : 0.f;
            }
        } else {
            int n  = tid >> 2;
            int kb = (tid & 3) * 4;
            int gn = n0 + n;
#pragma unroll
            for (int j = 0; j < 4; j++) {
                int gk = k0 + kb + j;
                Bs[kb + j][n] = (gn < N && gk < K) ? B[(long long)gn * ldb + gk] : 0.f;
            }
        }
        __syncthreads();

#pragma unroll
        for (int kk = 0; kk < BK; kk++) {
            float a[TM], b[TN];
#pragma unroll
            for (int i = 0; i < TM; i++) a[i] = As[kk][ty * TM + i];
#pragma unroll
            for (int j = 0; j < TN; j++) b[j] = Bs[kk][tx * TN + j];
#pragma unroll
            for (int i = 0; i < TM; i++)
#pragma unroll
                for (int j = 0; j < TN; j++)
                    acc[i][j] = fmaf(a[i], b[j], acc[i][j]);
        }
        __syncthreads();
    }

#pragma unroll
    for (int i = 0; i < TM; i++) {
        int gm = m0 + ty * TM + i;
        if (gm >= M) continue;
#pragma unroll
        for (int j = 0; j < TN; j++) {
            int gn = n0 + tx * TN + j;
            if (gn >= N) continue;
            float v = acc[i][j];
            if (BIASM == 1) v += bias[gm];
            if (BIASM == 2) v += bias[gn];
            C[(long long)gm * ldc + gn] = v;
        }
    }
}

// ---------------------------------------------------------------------------
__global__ void softmax_rows_kernel(float* __restrict__ att, int rows, int n)
{
    int warp = (blockIdx.x * blockDim.x + threadIdx.x) >> 5;
    int lane = threadIdx.x & 31;
    if (warp >= rows) return;
    float* row = att + (long long)warp * n;

    float vals[5];
    float mx = -1e30f;
#pragma unroll
    for (int i = 0; i < 5; i++) {
        int c = lane + 32 * i;
        vals[i] = (c < n) ? row[c] : -1e30f;
        mx = fmaxf(mx, vals[i]);
    }
#pragma unroll
    for (int o = 16; o; o >>= 1) mx = fmaxf(mx, __shfl_xor_sync(0xffffffffu, mx, o));

    float s = 0.f;
#pragma unroll
    for (int i = 0; i < 5; i++) {
        vals[i] = expf(vals[i] - mx);
        s += vals[i];
    }
#pragma unroll
    for (int o = 16; o; o >>= 1) s += __shfl_xor_sync(0xffffffffu, s, o);
    float inv = 1.f / s;
#pragma unroll
    for (int i = 0; i < 5; i++) {
        int c = lane + 32 * i;
        if (c < n) row[c] = vals[i] * inv;
    }
}

static inline int ceil_div(int a, int b) { return (a + b - 1) / b; }

extern "C" void kernel_launch(void* const* d_in, const int* in_sizes, int n_in,
                              void* d_out, int out_size)
{
    const float* x     = (const float*)d_in[0];
    const float* Wv    = (const float*)d_in[1];
    const float* bv    = (const float*)d_in[2];
    const float* Wq    = (const float*)d_in[3];
    const float* bq    = (const float*)d_in[4];
    const float* Wk    = (const float*)d_in[5];
    const float* bk    = (const float*)d_in[6];
    const float* gamma = (const float*)d_in[7];
    const float* W1    = (const float*)d_in[8];
    const float* b1    = (const float*)d_in[9];
    const float* W2    = (const float*)d_in[10];
    const float* b2    = (const float*)d_in[11];
    float* out = (float*)d_out;

    float *pv, *q, *k, *att, *aout, *h, *xT;
    cudaGetSymbolAddress((void**)&pv,  g_pv);
    cudaGetSymbolAddress((void**)&q,   g_q);
    cudaGetSymbolAddress((void**)&k,   g_k);
    cudaGetSymbolAddress((void**)&att, g_att);
    cudaGetSymbolAddress((void**)&aout,g_out);
    cudaGetSymbolAddress((void**)&h,   g_h);
    cudaGetSymbolAddress((void**)&xT,  g_xT);

    const long long sPV = (long long)CC * LL;
    const long long sAT = (long long)LL * LL;
    const long long sXT = (long long)LL * CIN;

    // 0) transpose x -> xT [B][L][CIN]
    transpose_x_kernel<<<dim3(ceil_div(LL, 32), CIN / 32, BATCH), dim3(32, 8)>>>(x, xT);

    // 1) pv[b][C,L] = Wv[C,CIN] * xT[b][L,CIN]^T + bv    (tensor MMA, bias per m)
    mma_gemm<1><<<dim3(ceil_div(LL, 128), CC / 128, BATCH), 256>>>(
        Wv, xT, bv, nullptr, nullptr, pv,
        CC, LL, CIN, CIN, CIN, LL, 0, sXT, sPV);

    // 2,3) q, k (SIMT)
    {
        dim3 grid(ceil_div(LL, BN), ceil_div(CC, BM), BATCH);
        sgemm_kernel<0,0,1><<<grid, 256>>>(Wq, pv, bq, q,
            CC, LL, CC, CC, LL, LL, 0, sPV, sPV);
        sgemm_kernel<0,0,1><<<grid, 256>>>(Wk, pv, bk, k,
            CC, LL, CC, CC, LL, LL, 0, sPV, sPV);
    }
    // 4) energy (SIMT)
    {
        dim3 grid(ceil_div(LL, BN), ceil_div(LL, BM), BATCH);
        sgemm_kernel<1,0,0><<<grid, 256>>>(q, k, nullptr, att,
            LL, LL, CC, LL, LL, LL, sPV, sPV, sAT);
    }
    // 5) softmax
    {
        int rows = BATCH * LL;
        int blocks = ceil_div(rows * 32, 256);
        softmax_rows_kernel<<<blocks, 256>>>(att, rows, LL);
    }
    // 6) attout + fused gamma residual: aout = gamma*(pv @ att^T) + pv  (MMA)
    mma_gemm<3><<<dim3(ceil_div(LL, 128), CC / 128, BATCH), 256>>>(
        pv, att, nullptr, gamma, pv, aout,
        CC, LL, LL, LL, LL, LL, sPV, sAT, sPV);

    // 7) fc1: h = aout_flat * W1^T + b1   (MMA, bias per n)
    mma_gemm<2><<<dim3(H1 / 128, BATCH / 128, 1), 256>>>(
        aout, W1, b1, nullptr, nullptr, h,
        BATCH, H1, CC * LL, CC * LL, CC * LL, H1, 0, 0, 0);

    // 8) fc2: out = h * W2^T + b2   (MMA, bias per n)
    mma_gemm<2><<<dim3(OUTN / 128, BATCH / 128, 1), 256>>>(
        h, W2, b2, nullptr, nullptr, out,
        BATCH, OUTN, H1, H1, H1, OUTN, 0, 0, 0);
}

// round 7
// speedup vs baseline: 2.7271x; 1.7621x over previous
#include <cuda_runtime.h>
#include <cuda_bf16.h>
#include <cstdint>

// Problem dims
#define BATCH 256
#define CIN   2048
#define LL    150
#define CC    256
#define H1    8192
#define OUTN  2048

// Scratch (device globals; no dynamic allocation allowed)
__device__ __align__(16) float g_pv [BATCH * CC * LL];
__device__ __align__(16) float g_q  [BATCH * CC * LL];
__device__ __align__(16) float g_k  [BATCH * CC * LL];
__device__ __align__(16) float g_att[BATCH * LL * LL];
__device__ __align__(16) float g_out[BATCH * CC * LL];
__device__ __align__(16) float g_h  [BATCH * H1];
__device__ __align__(16) float g_xT [BATCH * LL * CIN];

// ===========================================================================
// Warp-level bf16 MMA helpers (family-portable PTX: valid on plain sm_103)
// ===========================================================================
__device__ __forceinline__ uint32_t smem_u32(const void* p) {
    uint32_t a;
    asm("{ .reg .u64 t; cvta.to.shared.u64 t, %1; cvt.u32.u64 %0, t; }"
        : "=r"(a) : "l"(p));
    return a;
}
__device__ __forceinline__ void ldsm4(uint32_t& r0, uint32_t& r1, uint32_t& r2,
                                      uint32_t& r3, uint32_t addr) {
    asm volatile("ldmatrix.sync.aligned.m8n8.x4.shared.b16 {%0,%1,%2,%3}, [%4];"
                 : "=r"(r0), "=r"(r1), "=r"(r2), "=r"(r3) : "r"(addr));
}
__device__ __forceinline__ void mma_bf16(float* c, const uint32_t* a,
                                         const uint32_t* b) {
    asm volatile(
        "mma.sync.aligned.m16n8k16.row.col.f32.bf16.bf16.f32 "
        "{%0,%1,%2,%3}, {%4,%5,%6,%7}, {%8,%9}, {%0,%1,%2,%3};"
        : "+f"(c[0]), "+f"(c[1]), "+f"(c[2]), "+f"(c[3])
        : "r"(a[0]), "r"(a[1]), "r"(a[2]), "r"(a[3]), "r"(b[0]), "r"(b[1]));
}

// ===========================================================================
// Split-bf16 tensor-core GEMM, 2-stage software pipeline.
// C[M,N] = A[M,K] * B[N,K]^T (+ epilogue). A, B fp32 K-major.
// hi = trunc-to-bf16, lo = rn(x - hi); acc += Ahi*Bhi + Ahi*Blo + Alo*Bhi.
// Tile 128x128, BK=32, 256 threads (8 warps, warp tile 64x32).
// EPI: 0 none, 1 +bias[m], 2 +bias[n], 3 gamma[0]*acc + res[]
// ===========================================================================
#define RS 40                         // SMEM row stride (bf16 elems): 80B
#define TILE_EL (128 * RS)            // elems per tile
#define TILE_BY (TILE_EL * 2)         // 10240 bytes
#define STAGE_BY (4 * TILE_BY)        // AsHi, AsLo, BsHi, BsLo
#define PIPE_SMEM (2 * STAGE_BY)      // 81920 bytes

// Per-thread GMEM prefetch of a 128x32 fp32 tile (16 floats = 4 float4).
__device__ __forceinline__ void ldg_tile(const float* __restrict__ G, int rows,
        int Kdim, int ld, int row0, int k0, bool vecok, int tid, float4* out)
{
    int r  = tid >> 1;
    int cb = (tid & 1) * 16;
    int gr = row0 + r;
    const float* Grow = G + (long long)gr * ld;
    bool rok = gr < rows;
#pragma unroll
    for (int i = 0; i < 4; i++) {
        int gk = k0 + cb + i * 4;
        float4 v = make_float4(0.f, 0.f, 0.f, 0.f);
        if (rok) {
            if (vecok && gk + 3 < Kdim) {
                v = *reinterpret_cast<const float4*>(Grow + gk);
            } else {
                if (gk     < Kdim) v.x = Grow[gk];
                if (gk + 1 < Kdim) v.y = Grow[gk + 1];
                if (gk + 2 < Kdim) v.z = Grow[gk + 2];
                if (gk + 3 < Kdim) v.w = Grow[gk + 3];
            }
        }
        out[i] = v;
    }
}

// Convert 4x float4 to hi/lo bf16 and store to SMEM tile.
__device__ __forceinline__ void conv_store(const float4* in,
        __nv_bfloat16* hiS, __nv_bfloat16* loS, int tid)
{
    int r  = tid >> 1;
    int cb = (tid & 1) * 16;
#pragma unroll
    for (int i = 0; i < 4; i++) {
        float4 v = in[i];
        uint32_t b0 = __float_as_uint(v.x), b1 = __float_as_uint(v.y);
        uint32_t b2 = __float_as_uint(v.z), b3 = __float_as_uint(v.w);
        uint32_t hi01 = (b1 & 0xFFFF0000u) | (b0 >> 16);
        uint32_t hi23 = (b3 & 0xFFFF0000u) | (b2 >> 16);
        float l0 = v.x - __uint_as_float(b0 & 0xFFFF0000u);
        float l1 = v.y - __uint_as_float(b1 & 0xFFFF0000u);
        float l2 = v.z - __uint_as_float(b2 & 0xFFFF0000u);
        float l3 = v.w - __uint_as_float(b3 & 0xFFFF0000u);
        uint32_t lo01, lo23;
        asm("cvt.rn.bf16x2.f32 %0, %1, %2;" : "=r"(lo01) : "f"(l1), "f"(l0));
        asm("cvt.rn.bf16x2.f32 %0, %1, %2;" : "=r"(lo23) : "f"(l3), "f"(l2));
        int e = r * RS + cb + i * 4;
        *reinterpret_cast<uint2*>(hiS + e) = make_uint2(hi01, hi23);
        *reinterpret_cast<uint2*>(loS + e) = make_uint2(lo01, lo23);
    }
}

template<int EPI>
__global__ __launch_bounds__(256, 1)
void mma_gemm(const float* __restrict__ A, const float* __restrict__ B,
              const float* __restrict__ bias, const float* __restrict__ gamma,
              const float* __restrict__ res, float* __restrict__ C,
              int M, int N, int K, int lda, int ldb, int ldc,
              long long sA, long long sB, long long sC)
{
    extern __shared__ __align__(16) char dynsm[];
    __nv_bfloat16* sm = reinterpret_cast<__nv_bfloat16*>(dynsm);

    A += (long long)blockIdx.z * sA;
    B += (long long)blockIdx.z * sB;
    C += (long long)blockIdx.z * sC;
    if (EPI == 3) res += (long long)blockIdx.z * sC;

    const int tid  = threadIdx.x;
    const int wid  = tid >> 5;
    const int lane = tid & 31;
    const int wm = wid >> 2;
    const int wn = wid & 3;
    const int m0 = blockIdx.y * 128;
    const int n0 = blockIdx.x * 128;

    const bool vA = ((lda & 3) == 0);
    const bool vB = ((ldb & 3) == 0);

    const uint32_t smb = smem_u32(sm);

    // per-lane ldmatrix source coordinates (same mapping as validated R4)
    const int q = lane >> 3, r8 = lane & 7;
    const int a_row  = wm * 64 + ((q & 1) << 3) + r8;
    const int a_koff = (q >> 1) << 3;
    const int b_row  = wn * 32 + ((q >> 1) << 3) + r8;
    const int b_koff = (q & 1) << 3;

    float acc[4][4][4];
#pragma unroll
    for (int mi = 0; mi < 4; mi++)
#pragma unroll
        for (int ni = 0; ni < 4; ni++)
#pragma unroll
            for (int v = 0; v < 4; v++) acc[mi][ni][v] = 0.f;

    const int nch = (K + 31) >> 5;

    float4 pa[4], pb[4];
    // prologue: chunk 0 -> stage 0
    ldg_tile(A, M, K, lda, m0, 0, vA, tid, pa);
    ldg_tile(B, N, K, ldb, n0, 0, vB, tid, pb);
    {
        __nv_bfloat16* st = sm;
        conv_store(pa, st,               st + TILE_EL,     tid);
        conv_store(pb, st + 2 * TILE_EL, st + 3 * TILE_EL, tid);
    }
    __syncthreads();

    for (int ch = 0; ch < nch; ch++) {
        const int nxt = ch + 1;
        if (nxt < nch) {    // issue next chunk's LDGs (overlap with MMAs)
            ldg_tile(A, M, K, lda, m0, nxt * 32, vA, tid, pa);
            ldg_tile(B, N, K, ldb, n0, nxt * 32, vB, tid, pb);
        }

        // compute from stage ch&1
        const uint32_t stb = smb + (uint32_t)(ch & 1) * STAGE_BY;
        const uint32_t aHi = stb,                aLo = stb + TILE_BY;
        const uint32_t bHi = stb + 2 * TILE_BY,  bLo = stb + 3 * TILE_BY;

#pragma unroll
        for (int ks = 0; ks < 2; ks++) {
            uint32_t ah[4][4];
#pragma unroll
            for (int mi = 0; mi < 4; mi++) {
                uint32_t ad = aHi + (uint32_t)(((a_row + mi * 16) * RS
                                + ks * 16 + a_koff) * 2);
                ldsm4(ah[mi][0], ah[mi][1], ah[mi][2], ah[mi][3], ad);
            }
            uint32_t bh[4][2];
#pragma unroll
            for (int nb = 0; nb < 2; nb++) {
                uint32_t bd = bHi + (uint32_t)(((b_row + nb * 16) * RS
                                + ks * 16 + b_koff) * 2);
                uint32_t t0, t1, t2, t3;
                ldsm4(t0, t1, t2, t3, bd);
                bh[nb * 2][0] = t0; bh[nb * 2][1] = t1;
                bh[nb * 2 + 1][0] = t2; bh[nb * 2 + 1][1] = t3;
            }
#pragma unroll
            for (int mi = 0; mi < 4; mi++)
#pragma unroll
                for (int ni = 0; ni < 4; ni++)
                    mma_bf16(acc[mi][ni], ah[mi], bh[ni]);

            uint32_t bl[4][2];
#pragma unroll
            for (int nb = 0; nb < 2; nb++) {
                uint32_t bd = bLo + (uint32_t)(((b_row + nb * 16) * RS
                                + ks * 16 + b_koff) * 2);
                uint32_t t0, t1, t2, t3;
                ldsm4(t0, t1, t2, t3, bd);
                bl[nb * 2][0] = t0; bl[nb * 2][1] = t1;
                bl[nb * 2 + 1][0] = t2; bl[nb * 2 + 1][1] = t3;
            }
#pragma unroll
            for (int mi = 0; mi < 4; mi++)
#pragma unroll
                for (int ni = 0; ni < 4; ni++)
                    mma_bf16(acc[mi][ni], ah[mi], bl[ni]);   // reuse Ahi

            uint32_t al[4][4];
#pragma unroll
            for (int mi = 0; mi < 4; mi++) {
                uint32_t ad = aLo + (uint32_t)(((a_row + mi * 16) * RS
                                + ks * 16 + a_koff) * 2);
                ldsm4(al[mi][0], al[mi][1], al[mi][2], al[mi][3], ad);
            }
#pragma unroll
            for (int mi = 0; mi < 4; mi++)
#pragma unroll
                for (int ni = 0; ni < 4; ni++)
                    mma_bf16(acc[mi][ni], al[mi], bh[ni]);   // reuse Bhi
        }

        if (nxt < nch) {    // convert + store into the other stage
            __nv_bfloat16* st = sm + (nxt & 1) * (4 * TILE_EL);
            conv_store(pa, st,               st + TILE_EL,     tid);
            conv_store(pb, st + 2 * TILE_EL, st + 3 * TILE_EL, tid);
        }
        __syncthreads();
    }

    // epilogue
    const float gm_s = (EPI == 3) ? gamma[0] : 0.f;
#pragma unroll
    for (int mi = 0; mi < 4; mi++) {
        int gm0 = m0 + wm * 64 + mi * 16 + (lane >> 2);
#pragma unroll
        for (int half = 0; half < 2; half++) {
            int gm = gm0 + half * 8;
            if (gm >= M) continue;
            float bm = (EPI == 1) ? bias[gm] : 0.f;
#pragma unroll
            for (int ni = 0; ni < 4; ni++) {
                int gn = n0 + wn * 32 + ni * 8 + 2 * (lane & 3);
                if (gn >= N) continue;
                float v0 = acc[mi][ni][half * 2];
                float v1 = acc[mi][ni][half * 2 + 1];
                long long idx = (long long)gm * ldc + gn;
                if (EPI == 1) { v0 += bm; v1 += bm; }
                if (EPI == 2) { v0 += bias[gn]; v1 += (gn + 1 < N) ? bias[gn + 1] : 0.f; }
                if (EPI == 3) {
                    v0 = gm_s * v0 + res[idx];
                    if (gn + 1 < N) v1 = gm_s * v1 + res[idx + 1];
                }
                if (gn + 1 < N) {
                    *reinterpret_cast<float2*>(C + idx) = make_float2(v0, v1);
                } else {
                    C[idx] = v0;
                }
            }
        }
    }
}

// ===========================================================================
// x transpose: [B][CIN][L] -> [B][L][CIN]
// ===========================================================================
__global__ void transpose_x_kernel(const float* __restrict__ x, float* __restrict__ xT)
{
    __shared__ float t[32][33];
    int b  = blockIdx.z;
    int c0 = blockIdx.y * 32, l0 = blockIdx.x * 32;
    const float* xb = x + (long long)b * CIN * LL;
    float* xTb = xT + (long long)b * LL * CIN;
    int tx = threadIdx.x, ty = threadIdx.y;
#pragma unroll
    for (int i = ty; i < 32; i += 8) {
        int c = c0 + i, l = l0 + tx;
        t[i][tx] = (c < CIN && l < LL) ? xb[(long long)c * LL + l] : 0.f;
    }
    __syncthreads();
#pragma unroll
    for (int i = ty; i < 32; i += 8) {
        int l = l0 + i, c = c0 + tx;
        if (l < LL && c < CIN) xTb[(long long)l * CIN + c] = t[tx][i];
    }
}

// ===========================================================================
// SIMT SGEMM for the small attention GEMMs (q, k, energy)
// ===========================================================================
#define BM 128
#define BN 64
#define BK 16
#define TM 8
#define TN 4

template<int TA, int TB, int BIASM>
__global__ __launch_bounds__(256)
void sgemm_kernel(const float* __restrict__ A, const float* __restrict__ B,
                  const float* __restrict__ bias, float* __restrict__ C,
                  int M, int N, int K, int lda, int ldb, int ldc,
                  long long sA, long long sB, long long sC)
{
    A += (long long)blockIdx.z * sA;
    B += (long long)blockIdx.z * sB;
    C += (long long)blockIdx.z * sC;

    const int tid = threadIdx.x;
    const int tx = tid & 15;
    const int ty = tid >> 4;
    const int m0 = blockIdx.y * BM;
    const int n0 = blockIdx.x * BN;

    __shared__ float As[BK][BM];
    __shared__ float Bs[BK][BN];

    float acc[TM][TN];
#pragma unroll
    for (int i = 0; i < TM; i++)
#pragma unroll
        for (int j = 0; j < TN; j++) acc[i][j] = 0.f;

    for (int k0 = 0; k0 < K; k0 += BK) {
        if (TA == 0) {
            int m  = tid >> 1;
            int kb = (tid & 1) * 8;
            int gm = m0 + m;
#pragma unroll
            for (int j = 0; j < 8; j++) {
                int gk = k0 + kb + j;
                As[kb + j][m] = (gm < M && gk < K) ? A[(long long)gm * lda + gk] : 0.f;
            }
        } else {
            int kk = tid >> 4;
            int mb = (tid & 15) * 8;
            int gk = k0 + kk;
#pragma unroll
            for (int j = 0; j < 8; j++) {
                int gm = m0 + mb + j;
                As[kk][mb + j] = (gm < M && gk < K) ? A[(long long)gk * lda + gm] : 0.f;
            }
        }
        if (TB == 0) {
            int kk = tid >> 4;
            int nb = (tid & 15) * 4;
            int gk = k0 + kk;
#pragma unroll
            for (int j = 0; j < 4; j++) {
                int gn = n0 + nb + j;
                Bs[kk][nb + j] = (gk < K && gn < N) ? B[(long long)gk * ldb + gn] : 0.f;
            }
        } else {
            int n  = tid >> 2;
            int kb = (tid & 3) * 4;
            int gn = n0 + n;
#pragma unroll
            for (int j = 0; j < 4; j++) {
                int gk = k0 + kb + j;
                Bs[kb + j][n] = (gn < N && gk < K) ? B[(long long)gn * ldb + gk] : 0.f;
            }
        }
        __syncthreads();

#pragma unroll
        for (int kk = 0; kk < BK; kk++) {
            float a[TM], b[TN];
#pragma unroll
            for (int i = 0; i < TM; i++) a[i] = As[kk][ty * TM + i];
#pragma unroll
            for (int j = 0; j < TN; j++) b[j] = Bs[kk][tx * TN + j];
#pragma unroll
            for (int i = 0; i < TM; i++)
#pragma unroll
                for (int j = 0; j < TN; j++)
                    acc[i][j] = fmaf(a[i], b[j], acc[i][j]);
        }
        __syncthreads();
    }

#pragma unroll
    for (int i = 0; i < TM; i++) {
        int gm = m0 + ty * TM + i;
        if (gm >= M) continue;
#pragma unroll
        for (int j = 0; j < TN; j++) {
            int gn = n0 + tx * TN + j;
            if (gn >= N) continue;
            float v = acc[i][j];
            if (BIASM == 1) v += bias[gm];
            if (BIASM == 2) v += bias[gn];
            C[(long long)gm * ldc + gn] = v;
        }
    }
}

// ---------------------------------------------------------------------------
__global__ void softmax_rows_kernel(float* __restrict__ att, int rows, int n)
{
    int warp = (blockIdx.x * blockDim.x + threadIdx.x) >> 5;
    int lane = threadIdx.x & 31;
    if (warp >= rows) return;
    float* row = att + (long long)warp * n;

    float vals[5];
    float mx = -1e30f;
#pragma unroll
    for (int i = 0; i < 5; i++) {
        int c = lane + 32 * i;
        vals[i] = (c < n) ? row[c] : -1e30f;
        mx = fmaxf(mx, vals[i]);
    }
#pragma unroll
    for (int o = 16; o; o >>= 1) mx = fmaxf(mx, __shfl_xor_sync(0xffffffffu, mx, o));

    float s = 0.f;
#pragma unroll
    for (int i = 0; i < 5; i++) {
        vals[i] = expf(vals[i] - mx);
        s += vals[i];
    }
#pragma unroll
    for (int o = 16; o; o >>= 1) s += __shfl_xor_sync(0xffffffffu, s, o);
    float inv = 1.f / s;
#pragma unroll
    for (int i = 0; i < 5; i++) {
        int c = lane + 32 * i;
        if (c < n) row[c] = vals[i] * inv;
    }
}

static inline int ceil_div(int a, int b) { return (a + b - 1) / b; }

extern "C" void kernel_launch(void* const* d_in, const int* in_sizes, int n_in,
                              void* d_out, int out_size)
{
    const float* x     = (const float*)d_in[0];
    const float* Wv    = (const float*)d_in[1];
    const float* bv    = (const float*)d_in[2];
    const float* Wq    = (const float*)d_in[3];
    const float* bq    = (const float*)d_in[4];
    const float* Wk    = (const float*)d_in[5];
    const float* bk    = (const float*)d_in[6];
    const float* gamma = (const float*)d_in[7];
    const float* W1    = (const float*)d_in[8];
    const float* b1    = (const float*)d_in[9];
    const float* W2    = (const float*)d_in[10];
    const float* b2    = (const float*)d_in[11];
    float* out = (float*)d_out;

    float *pv, *q, *k, *att, *aout, *h, *xT;
    cudaGetSymbolAddress((void**)&pv,  g_pv);
    cudaGetSymbolAddress((void**)&q,   g_q);
    cudaGetSymbolAddress((void**)&k,   g_k);
    cudaGetSymbolAddress((void**)&att, g_att);
    cudaGetSymbolAddress((void**)&aout,g_out);
    cudaGetSymbolAddress((void**)&h,   g_h);
    cudaGetSymbolAddress((void**)&xT,  g_xT);

    static bool attr_done = false;
    if (!attr_done) {
        cudaFuncSetAttribute(mma_gemm<1>, cudaFuncAttributeMaxDynamicSharedMemorySize, PIPE_SMEM);
        cudaFuncSetAttribute(mma_gemm<2>, cudaFuncAttributeMaxDynamicSharedMemorySize, PIPE_SMEM);
        cudaFuncSetAttribute(mma_gemm<3>, cudaFuncAttributeMaxDynamicSharedMemorySize, PIPE_SMEM);
        attr_done = true;
    }

    const long long sPV = (long long)CC * LL;
    const long long sAT = (long long)LL * LL;
    const long long sXT = (long long)LL * CIN;

    // 0) transpose x -> xT [B][L][CIN]
    transpose_x_kernel<<<dim3(ceil_div(LL, 32), CIN / 32, BATCH), dim3(32, 8)>>>(x, xT);

    // 1) pv[b][C,L] = Wv[C,CIN] * xT[b][L,CIN]^T + bv    (MMA, bias per m)
    mma_gemm<1><<<dim3(ceil_div(LL, 128), CC / 128, BATCH), 256, PIPE_SMEM>>>(
        Wv, xT, bv, nullptr, nullptr, pv,
        CC, LL, CIN, CIN, CIN, LL, 0, sXT, sPV);

    // 2,3) q, k (SIMT)
    {
        dim3 grid(ceil_div(LL, BN), ceil_div(CC, BM), BATCH);
        sgemm_kernel<0,0,1><<<grid, 256>>>(Wq, pv, bq, q,
            CC, LL, CC, CC, LL, LL, 0, sPV, sPV);
        sgemm_kernel<0,0,1><<<grid, 256>>>(Wk, pv, bk, k,
            CC, LL, CC, CC, LL, LL, 0, sPV, sPV);
    }
    // 4) energy (SIMT)
    {
        dim3 grid(ceil_div(LL, BN), ceil_div(LL, BM), BATCH);
        sgemm_kernel<1,0,0><<<grid, 256>>>(q, k, nullptr, att,
            LL, LL, CC, LL, LL, LL, sPV, sPV, sAT);
    }
    // 5) softmax
    {
        int rows = BATCH * LL;
        int blocks = ceil_div(rows * 32, 256);
        softmax_rows_kernel<<<blocks, 256>>>(att, rows, LL);
    }
    // 6) attout + fused gamma residual (MMA): aout = gamma*(pv @ att^T) + pv
    mma_gemm<3><<<dim3(ceil_div(LL, 128), CC / 128, BATCH), 256, PIPE_SMEM>>>(
        pv, att, nullptr, gamma, pv, aout,
        CC, LL, LL, LL, LL, LL, sPV, sAT, sPV);

    // 7) fc1: h = aout_flat * W1^T + b1   (MMA, bias per n)
    mma_gemm<2><<<dim3(H1 / 128, BATCH / 128, 1), 256, PIPE_SMEM>>>(
        aout, W1, b1, nullptr, nullptr, h,
        BATCH, H1, CC * LL, CC * LL, CC * LL, H1, 0, 0, 0);

    // 8) fc2: out = h * W2^T + b2   (MMA, bias per n)
    mma_gemm<2><<<dim3(OUTN / 128, BATCH / 128, 1), 256, PIPE_SMEM>>>(
        h, W2, b2, nullptr, nullptr, out,
        BATCH, OUTN, H1, H1, H1, OUTN, 0, 0, 0);
}

// round 9
// speedup vs baseline: 2.8142x; 1.0320x over previous
#include <cuda_runtime.h>
#include <cuda_bf16.h>
#include <cstdint>

// Problem dims
#define BATCH 256
#define CIN   2048
#define LL    150
#define CC    256
#define H1    8192
#define OUTN  2048

// Scratch (device globals; no dynamic allocation allowed)
__device__ __align__(16) float g_pvT[BATCH * LL * CC];    // [B][L][C]
__device__ __align__(16) float g_pv [BATCH * CC * LL];    // [B][C][L]
__device__ __align__(16) float g_qT [BATCH * LL * CC];    // [B][L][C]
__device__ __align__(16) float g_kT [BATCH * LL * CC];    // [B][L][C]
__device__ __align__(16) float g_att[BATCH * LL * LL];    // [B][L][L]
__device__ __align__(16) float g_out[BATCH * CC * LL];    // [B][C][L]
__device__ __align__(16) float g_h  [BATCH * H1];
__device__ __align__(16) float g_xT [BATCH * LL * CIN];   // [B][L][CIN]

// ===========================================================================
// tf32 warp MMA (family-portable sm_80+ PTX, valid on plain sm_103 target)
// ===========================================================================
__device__ __forceinline__ void mma_tf32(float* c, const uint32_t* a,
                                         const uint32_t* b) {
    asm volatile(
        "mma.sync.aligned.m16n8k8.row.col.f32.tf32.tf32.f32 "
        "{%0,%1,%2,%3}, {%4,%5,%6,%7}, {%8,%9}, {%0,%1,%2,%3};"
        : "+f"(c[0]), "+f"(c[1]), "+f"(c[2]), "+f"(c[3])
        : "r"(a[0]), "r"(a[1]), "r"(a[2]), "r"(a[3]), "r"(b[0]), "r"(b[1]));
}
__device__ __forceinline__ uint32_t f2tf32(float x) {
    uint32_t o;
    asm("cvt.rna.tf32.f32 %0, %1;" : "=r"(o) : "f"(x));
    return o;
}

// ===========================================================================
// Single-pass tf32 tensor-core GEMM, 2-stage software pipeline.
// C[M,N] = A[M,K] * B[N,K]^T (+ epilogue). A, B fp32 K-major, rn-converted
// to tf32 in SMEM. Tile 128x128, BK=32, 256 threads (8 warps, 64x32/warp).
// EPI: 0 none, 1 +bias[m], 2 +bias[n], 3 gamma[0]*acc + res[]
// ===========================================================================
#define RSF   36                    // SMEM row stride (floats): conflict-free
#define TILEF (128 * RSF)           // 4608 floats / tile
#define STAGEF (2 * TILEF)          // A + B per stage
#define TF32_SMEM (2 * STAGEF * 4)  // 73728 bytes

// Per-thread GMEM fetch of a 128x32 fp32 tile (16 floats = 4 float4).
__device__ __forceinline__ void ldg_tile(const float* __restrict__ G, int rows,
        int Kdim, int ld, int row0, int k0, bool vecok, int tid, float4* out)
{
    int r  = tid >> 1;
    int cb = (tid & 1) * 16;
    int gr = row0 + r;
    const float* Grow = G + (long long)gr * ld;
    bool rok = gr < rows;
#pragma unroll
    for (int i = 0; i < 4; i++) {
        int gk = k0 + cb + i * 4;
        float4 v = make_float4(0.f, 0.f, 0.f, 0.f);
        if (rok) {
            if (vecok && gk + 3 < Kdim) {
                v = *reinterpret_cast<const float4*>(Grow + gk);
            } else {
                if (gk     < Kdim) v.x = Grow[gk];
                if (gk + 1 < Kdim) v.y = Grow[gk + 1];
                if (gk + 2 < Kdim) v.z = Grow[gk + 2];
                if (gk + 3 < Kdim) v.w = Grow[gk + 3];
            }
        }
        out[i] = v;
    }
}

// rn-convert 4x float4 to tf32 bits and store to SMEM tile (STS.128, no conflicts)
__device__ __forceinline__ void conv_store(const float4* in, float* S, int tid)
{
    int r  = tid >> 1;
    int cb = (tid & 1) * 16;
#pragma unroll
    for (int i = 0; i < 4; i++) {
        float4 v = in[i];
        uint4 t;
        t.x = f2tf32(v.x); t.y = f2tf32(v.y);
        t.z = f2tf32(v.z); t.w = f2tf32(v.w);
        *reinterpret_cast<uint4*>(S + r * RSF + cb + i * 4) = t;
    }
}

template<int EPI>
__global__ __launch_bounds__(256, 1)
void tf_gemm(const float* __restrict__ A, const float* __restrict__ B,
             const float* __restrict__ bias, const float* __restrict__ gamma,
             const float* __restrict__ res, float* __restrict__ C,
             int M, int N, int K, int lda, int ldb, int ldc,
             long long sA, long long sB, long long sC)
{
    extern __shared__ __align__(16) float sm[];

    A += (long long)blockIdx.z * sA;
    B += (long long)blockIdx.z * sB;
    C += (long long)blockIdx.z * sC;
    if (EPI == 3) res += (long long)blockIdx.z * sC;

    const int tid  = threadIdx.x;
    const int wid  = tid >> 5;
    const int lane = tid & 31;
    const int wm = wid >> 2;          // 0..1 -> m offset *64
    const int wn = wid & 3;           // 0..3 -> n offset *32
    const int m0 = blockIdx.y * 128;
    const int n0 = blockIdx.x * 128;

    const bool vA = ((lda & 3) == 0);
    const bool vB = ((ldb & 3) == 0);

    // tf32 m16n8k8 fragment coordinates
    const int ag = lane >> 2;         // group id (row within 8)
    const int ac = lane & 3;          // thread-in-group (col within 4)

    float acc[4][4][4];
#pragma unroll
    for (int mi = 0; mi < 4; mi++)
#pragma unroll
        for (int ni = 0; ni < 4; ni++)
#pragma unroll
            for (int v = 0; v < 4; v++) acc[mi][ni][v] = 0.f;

    const int nch = (K + 31) >> 5;

    float4 pa[4], pb[4];
    ldg_tile(A, M, K, lda, m0, 0, vA, tid, pa);
    ldg_tile(B, N, K, ldb, n0, 0, vB, tid, pb);
    conv_store(pa, sm,         tid);
    conv_store(pb, sm + TILEF, tid);
    __syncthreads();

    for (int ch = 0; ch < nch; ch++) {
        const int nxt = ch + 1;
        if (nxt < nch) {
            ldg_tile(A, M, K, lda, m0, nxt * 32, vA, tid, pa);
            ldg_tile(B, N, K, ldb, n0, nxt * 32, vB, tid, pb);
        }

        const float* SA = sm + (ch & 1) * STAGEF;
        const uint32_t* UA = reinterpret_cast<const uint32_t*>(SA);
        const uint32_t* UB = UA + TILEF;

#pragma unroll
        for (int ks = 0; ks < 4; ks++) {
            const int kc = ks * 8 + ac;
            uint32_t af[4][4];
#pragma unroll
            for (int mi = 0; mi < 4; mi++) {
                int rr = wm * 64 + mi * 16 + ag;
                af[mi][0] = UA[rr * RSF + kc];
                af[mi][1] = UA[(rr + 8) * RSF + kc];
                af[mi][2] = UA[rr * RSF + kc + 4];
                af[mi][3] = UA[(rr + 8) * RSF + kc + 4];
            }
            uint32_t bf[4][2];
#pragma unroll
            for (int ni = 0; ni < 4; ni++) {
                int nn = wn * 32 + ni * 8 + ag;
                bf[ni][0] = UB[nn * RSF + kc];
                bf[ni][1] = UB[nn * RSF + kc + 4];
            }
#pragma unroll
            for (int mi = 0; mi < 4; mi++)
#pragma unroll
                for (int ni = 0; ni < 4; ni++)
                    mma_tf32(acc[mi][ni], af[mi], bf[ni]);
        }

        if (nxt < nch) {
            float* st = sm + (nxt & 1) * STAGEF;
            conv_store(pa, st,         tid);
            conv_store(pb, st + TILEF, tid);
        }
        __syncthreads();
    }

    // epilogue (C fragment: rows g, g+8; cols 2t, 2t+1)
    const float gm_s = (EPI == 3) ? gamma[0] : 0.f;
#pragma unroll
    for (int mi = 0; mi < 4; mi++) {
        int gm0 = m0 + wm * 64 + mi * 16 + ag;
#pragma unroll
        for (int half = 0; half < 2; half++) {
            int gm = gm0 + half * 8;
            if (gm >= M) continue;
            float bm = (EPI == 1) ? bias[gm] : 0.f;
#pragma unroll
            for (int ni = 0; ni < 4; ni++) {
                int gn = n0 + wn * 32 + ni * 8 + 2 * ac;
                if (gn >= N) continue;
                float v0 = acc[mi][ni][half * 2];
                float v1 = acc[mi][ni][half * 2 + 1];
                long long idx = (long long)gm * ldc + gn;
                if (EPI == 1) { v0 += bm; v1 += bm; }
                if (EPI == 2) { v0 += bias[gn]; v1 += (gn + 1 < N) ? bias[gn + 1] : 0.f; }
                if (EPI == 3) {
                    v0 = gm_s * v0 + res[idx];
                    if (gn + 1 < N) v1 = gm_s * v1 + res[idx + 1];
                }
                if (gn + 1 < N) {
                    *reinterpret_cast<float2*>(C + idx) = make_float2(v0, v1);
                } else {
                    C[idx] = v0;
                }
            }
        }
    }
}

// ===========================================================================
// x transpose: [B][CIN][L] -> [B][L][CIN]
// ===========================================================================
__global__ void transpose_x_kernel(const float* __restrict__ x, float* __restrict__ xT)
{
    __shared__ float t[32][33];
    int b  = blockIdx.z;
    int c0 = blockIdx.y * 32, l0 = blockIdx.x * 32;
    const float* xb = x + (long long)b * CIN * LL;
    float* xTb = xT + (long long)b * LL * CIN;
    int tx = threadIdx.x, ty = threadIdx.y;
#pragma unroll
    for (int i = ty; i < 32; i += 8) {
        int c = c0 + i, l = l0 + tx;
        t[i][tx] = (c < CIN && l < LL) ? xb[(long long)c * LL + l] : 0.f;
    }
    __syncthreads();
#pragma unroll
    for (int i = ty; i < 32; i += 8) {
        int l = l0 + i, c = c0 + tx;
        if (l < LL && c < CIN) xTb[(long long)l * CIN + c] = t[tx][i];
    }
}

// pvT [B][L=150][C=256] -> pv [B][C=256][L=150]
__global__ void transpose_pv_kernel(const float* __restrict__ in, float* __restrict__ out)
{
    __shared__ float t[32][33];
    int b  = blockIdx.z;
    int c0 = blockIdx.x * 32, l0 = blockIdx.y * 32;
    const float* ib = in + (long long)b * LL * CC;
    float* ob = out + (long long)b * CC * LL;
    int tx = threadIdx.x, ty = threadIdx.y;
#pragma unroll
    for (int i = ty; i < 32; i += 8) {
        int l = l0 + i;
        if (l < LL) t[i][tx] = ib[(long long)l * CC + c0 + tx];
    }
    __syncthreads();
#pragma unroll
    for (int i = ty; i < 32; i += 8) {
        int l = l0 + tx;
        if (l < LL) ob[(long long)(c0 + i) * LL + l] = t[tx][i];
    }
}

// ---------------------------------------------------------------------------
__global__ void softmax_rows_kernel(float* __restrict__ att, int rows, int n)
{
    int warp = (blockIdx.x * blockDim.x + threadIdx.x) >> 5;
    int lane = threadIdx.x & 31;
    if (warp >= rows) return;
    float* row = att + (long long)warp * n;

    float vals[5];
    float mx = -1e30f;
#pragma unroll
    for (int i = 0; i < 5; i++) {
        int c = lane + 32 * i;
        vals[i] = (c < n) ? row[c] : -1e30f;
        mx = fmaxf(mx, vals[i]);
    }
#pragma unroll
    for (int o = 16; o; o >>= 1) mx = fmaxf(mx, __shfl_xor_sync(0xffffffffu, mx, o));

    float s = 0.f;
#pragma unroll
    for (int i = 0; i < 5; i++) {
        vals[i] = expf(vals[i] - mx);
        s += vals[i];
    }
#pragma unroll
    for (int o = 16; o; o >>= 1) s += __shfl_xor_sync(0xffffffffu, s, o);
    float inv = 1.f / s;
#pragma unroll
    for (int i = 0; i < 5; i++) {
        int c = lane + 32 * i;
        if (c < n) row[c] = vals[i] * inv;
    }
}

static inline int ceil_div(int a, int b) { return (a + b - 1) / b; }

extern "C" void kernel_launch(void* const* d_in, const int* in_sizes, int n_in,
                              void* d_out, int out_size)
{
    const float* x     = (const float*)d_in[0];
    const float* Wv    = (const float*)d_in[1];
    const float* bv    = (const float*)d_in[2];
    const float* Wq    = (const float*)d_in[3];
    const float* bq    = (const float*)d_in[4];
    const float* Wk    = (const float*)d_in[5];
    const float* bk    = (const float*)d_in[6];
    const float* gamma = (const float*)d_in[7];
    const float* W1    = (const float*)d_in[8];
    const float* b1    = (const float*)d_in[9];
    const float* W2    = (const float*)d_in[10];
    const float* b2    = (const float*)d_in[11];
    float* out = (float*)d_out;

    float *pvT, *pv, *qT, *kT, *att, *aout, *h, *xT;
    cudaGetSymbolAddress((void**)&pvT, g_pvT);
    cudaGetSymbolAddress((void**)&pv,  g_pv);
    cudaGetSymbolAddress((void**)&qT,  g_qT);
    cudaGetSymbolAddress((void**)&kT,  g_kT);
    cudaGetSymbolAddress((void**)&att, g_att);
    cudaGetSymbolAddress((void**)&aout,g_out);
    cudaGetSymbolAddress((void**)&h,   g_h);
    cudaGetSymbolAddress((void**)&xT,  g_xT);

    static bool attr_done = false;
    if (!attr_done) {
        cudaFuncSetAttribute(tf_gemm<0>, cudaFuncAttributeMaxDynamicSharedMemorySize, TF32_SMEM);
        cudaFuncSetAttribute(tf_gemm<1>, cudaFuncAttributeMaxDynamicSharedMemorySize, TF32_SMEM);
        cudaFuncSetAttribute(tf_gemm<2>, cudaFuncAttributeMaxDynamicSharedMemorySize, TF32_SMEM);
        cudaFuncSetAttribute(tf_gemm<3>, cudaFuncAttributeMaxDynamicSharedMemorySize, TF32_SMEM);
        attr_done = true;
    }

    const long long sPV = (long long)CC * LL;    // 38400 (pv, pvT, qT, kT, aout)
    const long long sAT = (long long)LL * LL;    // 22500
    const long long sXT = (long long)LL * CIN;   // 307200

    // 0) transpose x -> xT [B][L][CIN]
    transpose_x_kernel<<<dim3(ceil_div(LL, 32), CIN / 32, BATCH), dim3(32, 8)>>>(x, xT);

    // 1) pvT[b][L,C] = xT[b] @ Wv^T + bv[n]
    tf_gemm<2><<<dim3(CC / 128, ceil_div(LL, 128), BATCH), 256, TF32_SMEM>>>(
        xT, Wv, bv, nullptr, nullptr, pvT,
        LL, CC, CIN, CIN, CIN, CC, sXT, 0, sPV);

    // 2) pv[b][C,L] = pvT^T
    transpose_pv_kernel<<<dim3(CC / 32, ceil_div(LL, 32), BATCH), dim3(32, 8)>>>(pvT, pv);

    // 3) qT[b][L,C] = pvT @ Wq^T + bq[n];  kT likewise
    {
        dim3 grid(CC / 128, ceil_div(LL, 128), BATCH);
        tf_gemm<2><<<grid, 256, TF32_SMEM>>>(pvT, Wq, bq, nullptr, nullptr, qT,
            LL, CC, CC, CC, CC, CC, sPV, 0, sPV);
        tf_gemm<2><<<grid, 256, TF32_SMEM>>>(pvT, Wk, bk, nullptr, nullptr, kT,
            LL, CC, CC, CC, CC, CC, sPV, 0, sPV);
    }
    // 4) energy[b][L,L] = qT @ kT^T
    tf_gemm<0><<<dim3(ceil_div(LL, 128), ceil_div(LL, 128), BATCH), 256, TF32_SMEM>>>(
        qT, kT, nullptr, nullptr, nullptr, att,
        LL, LL, CC, CC, CC, LL, sPV, sPV, sAT);

    // 5) softmax rows
    {
        int rows = BATCH * LL;
        int blocks = ceil_div(rows * 32, 256);
        softmax_rows_kernel<<<blocks, 256>>>(att, rows, LL);
    }
    // 6) aout[b][C,L] = gamma * (pv @ att^T) + pv
    tf_gemm<3><<<dim3(ceil_div(LL, 128), CC / 128, BATCH), 256, TF32_SMEM>>>(
        pv, att, nullptr, gamma, pv, aout,
        CC, LL, LL, LL, LL, LL, sPV, sAT, sPV);

    // 7) fc1: h = aout_flat @ W1^T + b1
    tf_gemm<2><<<dim3(H1 / 128, BATCH / 128, 1), 256, TF32_SMEM>>>(
        aout, W1, b1, nullptr, nullptr, h,
        BATCH, H1, CC * LL, CC * LL, CC * LL, H1, 0, 0, 0);

    // 8) fc2: out = h @ W2^T + b2
    tf_gemm<2><<<dim3(OUTN / 128, BATCH / 128, 1), 256, TF32_SMEM>>>(
        h, W2, b2, nullptr, nullptr, out,
        BATCH, OUTN, H1, H1, H1, OUTN, 0, 0, 0);
}

// round 10
// speedup vs baseline: 3.1502x; 1.1194x over previous
#include <cuda_runtime.h>
#include <cuda_bf16.h>
#include <cstdint>

// Problem dims
#define BATCH 256
#define CIN   2048
#define LL    150
#define LP    152      // padded L stride (16B-aligned rows for cp.async)
#define CC    256
#define H1    8192
#define OUTN  2048

// Scratch (device globals; no dynamic allocation allowed)
__device__ __align__(16) float g_pvT[BATCH * LL * CC];    // [B][L][C]
__device__ __align__(16) float g_pv [BATCH * CC * LP];    // [B][C][LP]
__device__ __align__(16) float g_qT [BATCH * LL * CC];    // [B][L][C]
__device__ __align__(16) float g_kT [BATCH * LL * CC];    // [B][L][C]
__device__ __align__(16) float g_att[BATCH * LL * LP];    // [B][L][LP]
__device__ __align__(16) float g_out[BATCH * CC * LL];    // [B][C][L] packed
__device__ __align__(16) float g_h  [BATCH * H1];
__device__ __align__(16) float g_xT [BATCH * LL * CIN];   // [B][L][CIN]

// ===========================================================================
// tf32 warp MMA + cp.async helpers (family-portable PTX, plain sm_103 OK)
// ===========================================================================
__device__ __forceinline__ void mma_tf32(float* c, const uint32_t* a,
                                         const uint32_t* b) {
    asm volatile(
        "mma.sync.aligned.m16n8k8.row.col.f32.tf32.tf32.f32 "
        "{%0,%1,%2,%3}, {%4,%5,%6,%7}, {%8,%9}, {%0,%1,%2,%3};"
        : "+f"(c[0]), "+f"(c[1]), "+f"(c[2]), "+f"(c[3])
        : "r"(a[0]), "r"(a[1]), "r"(a[2]), "r"(a[3]), "r"(b[0]), "r"(b[1]));
}
__device__ __forceinline__ uint32_t f2tf32(float x) {
    uint32_t o;
    asm("cvt.rna.tf32.f32 %0, %1;" : "=r"(o) : "f"(x));
    return o;
}
__device__ __forceinline__ uint32_t smem_u32(const void* p) {
    uint32_t a;
    asm("{ .reg .u64 t; cvta.to.shared.u64 t, %1; cvt.u32.u64 %0, t; }"
        : "=r"(a) : "l"(p));
    return a;
}
#define CP_COMMIT() asm volatile("cp.async.commit_group;" ::: "memory")

// ===========================================================================
// Single-pass tf32 GEMM, cp.async 2-stage pipeline, 2 CTAs/SM.
// C[M,N] = A[M,K] * B[N,K]^T (+ epilogue). A, B fp32 K-major (rows 16B
// aligned), raw fp32 staged in SMEM, cvt.rna.tf32 applied in registers.
// Tile 128x128, BK=32, 256 threads (8 warps, 64x32/warp).
// EPI: 0 none, 1 +bias[m], 2 +bias[n], 3 gamma[0]*acc + res[] (ldr/sR)
// ===========================================================================
#define RSF    36                    // SMEM row stride (floats): conflict-free
#define TILEF  (128 * RSF)           // 4608 floats / tile
#define TILE_BY (TILEF * 4)          // 18432 bytes
#define STAGE_BY (2 * TILE_BY)       // A + B per stage
#define TF32_SMEM (2 * STAGE_BY)     // 73728 bytes

// cp.async of a 128x32 fp32 tile (4 x 16B per thread), zfill at edges.
__device__ __forceinline__ void cp_tile(const float* __restrict__ G, int rows,
        int Kdim, int ld, int row0, int k0, uint32_t dstBase, int tid)
{
    const int r  = tid >> 1;
    const int cb = (tid & 1) * 16;
    const int gr = row0 + r;
    const bool rok = gr < rows;
    const float* Grow = G + (long long)(rok ? gr : 0) * ld;
    const uint32_t drow = dstBase + (uint32_t)(r * RSF + cb) * 4u;
#pragma unroll
    for (int i = 0; i < 4; i++) {
        int gk = k0 + cb + i * 4;
        int rem = Kdim - gk;
        int sz = rok ? (rem >= 4 ? 16 : (rem > 0 ? rem * 4 : 0)) : 0;
        const float* src = (sz > 0) ? (Grow + gk) : G;
        asm volatile("cp.async.cg.shared.global [%0], [%1], 16, %2;"
                     :: "r"(drow + (uint32_t)i * 16u), "l"(src), "r"(sz));
    }
}

template<int EPI>
__global__ __launch_bounds__(256, 2)
void tf_gemm(const float* __restrict__ A, const float* __restrict__ B,
             const float* __restrict__ bias, const float* __restrict__ gamma,
             const float* __restrict__ res, float* __restrict__ C,
             int M, int N, int K, int lda, int ldb, int ldc, int ldr,
             long long sA, long long sB, long long sC, long long sR)
{
    extern __shared__ __align__(16) float sm[];

    A += (long long)blockIdx.z * sA;
    B += (long long)blockIdx.z * sB;
    C += (long long)blockIdx.z * sC;
    if (EPI == 3) res += (long long)blockIdx.z * sR;

    const int tid  = threadIdx.x;
    const int wid  = tid >> 5;
    const int lane = tid & 31;
    const int wm = wid >> 2;          // 0..1 -> m offset *64
    const int wn = wid & 3;           // 0..3 -> n offset *32
    const int m0 = blockIdx.y * 128;
    const int n0 = blockIdx.x * 128;

    const uint32_t smb = smem_u32(sm);

    // tf32 m16n8k8 fragment coordinates
    const int ag = lane >> 2;         // row-in-8
    const int ac = lane & 3;          // col-in-4

    float acc[4][4][4];
#pragma unroll
    for (int mi = 0; mi < 4; mi++)
#pragma unroll
        for (int ni = 0; ni < 4; ni++)
#pragma unroll
            for (int v = 0; v < 4; v++) acc[mi][ni][v] = 0.f;

    const int nch = (K + 31) >> 5;

    // prologue: chunk 0 -> stage 0
    cp_tile(A, M, K, lda, m0, 0, smb,           tid);
    cp_tile(B, N, K, ldb, n0, 0, smb + TILE_BY, tid);
    CP_COMMIT();

    for (int ch = 0; ch < nch; ch++) {
        const int nxt = ch + 1;
        if (nxt < nch) {
            const uint32_t st = smb + (uint32_t)(nxt & 1) * STAGE_BY;
            cp_tile(A, M, K, lda, m0, nxt * 32, st,           tid);
            cp_tile(B, N, K, ldb, n0, nxt * 32, st + TILE_BY, tid);
            CP_COMMIT();
            asm volatile("cp.async.wait_group 1;" ::: "memory");
        } else {
            asm volatile("cp.async.wait_group 0;" ::: "memory");
        }
        __syncthreads();

        const float* SA = sm + (ch & 1) * (STAGE_BY / 4);
        const float* SB = SA + TILEF;

#pragma unroll
        for (int ks = 0; ks < 4; ks++) {
            const int kc = ks * 8 + ac;
            uint32_t af[4][4];
#pragma unroll
            for (int mi = 0; mi < 4; mi++) {
                int rr = wm * 64 + mi * 16 + ag;
                af[mi][0] = f2tf32(SA[rr * RSF + kc]);
                af[mi][1] = f2tf32(SA[(rr + 8) * RSF + kc]);
                af[mi][2] = f2tf32(SA[rr * RSF + kc + 4]);
                af[mi][3] = f2tf32(SA[(rr + 8) * RSF + kc + 4]);
            }
            uint32_t bf[4][2];
#pragma unroll
            for (int ni = 0; ni < 4; ni++) {
                int nn = wn * 32 + ni * 8 + ag;
                bf[ni][0] = f2tf32(SB[nn * RSF + kc]);
                bf[ni][1] = f2tf32(SB[nn * RSF + kc + 4]);
            }
#pragma unroll
            for (int mi = 0; mi < 4; mi++)
#pragma unroll
                for (int ni = 0; ni < 4; ni++)
                    mma_tf32(acc[mi][ni], af[mi], bf[ni]);
        }
        __syncthreads();
    }

    // epilogue (C fragment: rows ag, ag+8; cols 2*ac, 2*ac+1)
    const float gm_s = (EPI == 3) ? gamma[0] : 0.f;
#pragma unroll
    for (int mi = 0; mi < 4; mi++) {
        int gm0 = m0 + wm * 64 + mi * 16 + ag;
#pragma unroll
        for (int half = 0; half < 2; half++) {
            int gm = gm0 + half * 8;
            if (gm >= M) continue;
            float bm = (EPI == 1) ? bias[gm] : 0.f;
#pragma unroll
            for (int ni = 0; ni < 4; ni++) {
                int gn = n0 + wn * 32 + ni * 8 + 2 * ac;
                if (gn >= N) continue;
                float v0 = acc[mi][ni][half * 2];
                float v1 = acc[mi][ni][half * 2 + 1];
                long long idx = (long long)gm * ldc + gn;
                if (EPI == 1) { v0 += bm; v1 += bm; }
                if (EPI == 2) { v0 += bias[gn]; v1 += (gn + 1 < N) ? bias[gn + 1] : 0.f; }
                if (EPI == 3) {
                    long long ridx = (long long)gm * ldr + gn;
                    v0 = gm_s * v0 + res[ridx];
                    if (gn + 1 < N) v1 = gm_s * v1 + res[ridx + 1];
                }
                if (gn + 1 < N) {
                    *reinterpret_cast<float2*>(C + idx) = make_float2(v0, v1);
                } else {
                    C[idx] = v0;
                }
            }
        }
    }
}

// ===========================================================================
// x transpose: [B][CIN][L] -> [B][L][CIN]
// ===========================================================================
__global__ void transpose_x_kernel(const float* __restrict__ x, float* __restrict__ xT)
{
    __shared__ float t[32][33];
    int b  = blockIdx.z;
    int c0 = blockIdx.y * 32, l0 = blockIdx.x * 32;
    const float* xb = x + (long long)b * CIN * LL;
    float* xTb = xT + (long long)b * LL * CIN;
    int tx = threadIdx.x, ty = threadIdx.y;
#pragma unroll
    for (int i = ty; i < 32; i += 8) {
        int c = c0 + i, l = l0 + tx;
        t[i][tx] = (c < CIN && l < LL) ? xb[(long long)c * LL + l] : 0.f;
    }
    __syncthreads();
#pragma unroll
    for (int i = ty; i < 32; i += 8) {
        int l = l0 + i, c = c0 + tx;
        if (l < LL && c < CIN) xTb[(long long)l * CIN + c] = t[tx][i];
    }
}

// pvT [B][L][C] -> pv [B][C][LP] (padded L stride)
__global__ void transpose_pv_kernel(const float* __restrict__ in, float* __restrict__ out)
{
    __shared__ float t[32][33];
    int b  = blockIdx.z;
    int c0 = blockIdx.x * 32, l0 = blockIdx.y * 32;
    const float* ib = in + (long long)b * LL * CC;
    float* ob = out + (long long)b * CC * LP;
    int tx = threadIdx.x, ty = threadIdx.y;
#pragma unroll
    for (int i = ty; i < 32; i += 8) {
        int l = l0 + i;
        if (l < LL) t[i][tx] = ib[(long long)l * CC + c0 + tx];
    }
    __syncthreads();
#pragma unroll
    for (int i = ty; i < 32; i += 8) {
        int l = l0 + tx;
        if (l < LL) ob[(long long)(c0 + i) * LP + l] = t[tx][i];
    }
}

// ---------------------------------------------------------------------------
// Softmax over rows of length LL with row stride LP; one warp per row.
// ---------------------------------------------------------------------------
__global__ void softmax_rows_kernel(float* __restrict__ att, int rows)
{
    int warp = (blockIdx.x * blockDim.x + threadIdx.x) >> 5;
    int lane = threadIdx.x & 31;
    if (warp >= rows) return;
    float* row = att + (long long)warp * LP;

    float vals[5];
    float mx = -1e30f;
#pragma unroll
    for (int i = 0; i < 5; i++) {
        int c = lane + 32 * i;
        vals[i] = (c < LL) ? row[c] : -1e30f;
        mx = fmaxf(mx, vals[i]);
    }
#pragma unroll
    for (int o = 16; o; o >>= 1) mx = fmaxf(mx, __shfl_xor_sync(0xffffffffu, mx, o));

    float s = 0.f;
#pragma unroll
    for (int i = 0; i < 5; i++) {
        vals[i] = expf(vals[i] - mx);
        s += vals[i];
    }
#pragma unroll
    for (int o = 16; o; o >>= 1) s += __shfl_xor_sync(0xffffffffu, s, o);
    float inv = 1.f / s;
#pragma unroll
    for (int i = 0; i < 5; i++) {
        int c = lane + 32 * i;
        if (c < LL) row[c] = vals[i] * inv;
    }
}

static inline int ceil_div(int a, int b) { return (a + b - 1) / b; }

extern "C" void kernel_launch(void* const* d_in, const int* in_sizes, int n_in,
                              void* d_out, int out_size)
{
    const float* x     = (const float*)d_in[0];
    const float* Wv    = (const float*)d_in[1];
    const float* bv    = (const float*)d_in[2];
    const float* Wq    = (const float*)d_in[3];
    const float* bq    = (const float*)d_in[4];
    const float* Wk    = (const float*)d_in[5];
    const float* bk    = (const float*)d_in[6];
    const float* gamma = (const float*)d_in[7];
    const float* W1    = (const float*)d_in[8];
    const float* b1    = (const float*)d_in[9];
    const float* W2    = (const float*)d_in[10];
    const float* b2    = (const float*)d_in[11];
    float* out = (float*)d_out;

    float *pvT, *pv, *qT, *kT, *att, *aout, *h, *xT;
    cudaGetSymbolAddress((void**)&pvT, g_pvT);
    cudaGetSymbolAddress((void**)&pv,  g_pv);
    cudaGetSymbolAddress((void**)&qT,  g_qT);
    cudaGetSymbolAddress((void**)&kT,  g_kT);
    cudaGetSymbolAddress((void**)&att, g_att);
    cudaGetSymbolAddress((void**)&aout,g_out);
    cudaGetSymbolAddress((void**)&h,   g_h);
    cudaGetSymbolAddress((void**)&xT,  g_xT);

    static bool attr_done = false;
    if (!attr_done) {
        cudaFuncSetAttribute(tf_gemm<0>, cudaFuncAttributeMaxDynamicSharedMemorySize, TF32_SMEM);
        cudaFuncSetAttribute(tf_gemm<1>, cudaFuncAttributeMaxDynamicSharedMemorySize, TF32_SMEM);
        cudaFuncSetAttribute(tf_gemm<2>, cudaFuncAttributeMaxDynamicSharedMemorySize, TF32_SMEM);
        cudaFuncSetAttribute(tf_gemm<3>, cudaFuncAttributeMaxDynamicSharedMemorySize, TF32_SMEM);
        attr_done = true;
    }

    const long long sPVT = (long long)LL * CC;   // 38400
    const long long sPVp = (long long)CC * LP;   // 38912
    const long long sATp = (long long)LL * LP;   // 22800
    const long long sXT  = (long long)LL * CIN;  // 307200
    const long long sAO  = (long long)CC * LL;   // 38400 (packed)

    // 0) transpose x -> xT [B][L][CIN]
    transpose_x_kernel<<<dim3(ceil_div(LL, 32), CIN / 32, BATCH), dim3(32, 8)>>>(x, xT);

    // 1) pvT[b][L,C] = xT[b] @ Wv^T + bv[n]
    tf_gemm<2><<<dim3(CC / 128, ceil_div(LL, 128), BATCH), 256, TF32_SMEM>>>(
        xT, Wv, bv, nullptr, nullptr, pvT,
        LL, CC, CIN, CIN, CIN, CC, 0, sXT, 0, sPVT, 0);

    // 2) pv[b][C,LP] = pvT^T
    transpose_pv_kernel<<<dim3(CC / 32, ceil_div(LL, 32), BATCH), dim3(32, 8)>>>(pvT, pv);

    // 3) qT, kT
    {
        dim3 grid(CC / 128, ceil_div(LL, 128), BATCH);
        tf_gemm<2><<<grid, 256, TF32_SMEM>>>(pvT, Wq, bq, nullptr, nullptr, qT,
            LL, CC, CC, CC, CC, CC, 0, sPVT, 0, sPVT, 0);
        tf_gemm<2><<<grid, 256, TF32_SMEM>>>(pvT, Wk, bk, nullptr, nullptr, kT,
            LL, CC, CC, CC, CC, CC, 0, sPVT, 0, sPVT, 0);
    }
    // 4) energy[b][L,LP] = qT @ kT^T
    tf_gemm<0><<<dim3(ceil_div(LL, 128), ceil_div(LL, 128), BATCH), 256, TF32_SMEM>>>(
        qT, kT, nullptr, nullptr, nullptr, att,
        LL, LL, CC, CC, CC, LP, 0, sPVT, sPVT, sATp, 0);

    // 5) softmax rows
    {
        int rows = BATCH * LL;
        int blocks = ceil_div(rows * 32, 256);
        softmax_rows_kernel<<<blocks, 256>>>(att, rows);
    }
    // 6) aout[b][C,L] = gamma * (pv @ att^T) + pv   (aout packed for fc1)
    tf_gemm<3><<<dim3(ceil_div(LL, 128), CC / 128, BATCH), 256, TF32_SMEM>>>(
        pv, att, nullptr, gamma, pv, aout,
        CC, LL, LL, LP, LP, LL, LP, sPVp, sATp, sAO, sPVp);

    // 7) fc1: h = aout_flat @ W1^T + b1
    tf_gemm<2><<<dim3(H1 / 128, BATCH / 128, 1), 256, TF32_SMEM>>>(
        aout, W1, b1, nullptr, nullptr, h,
        BATCH, H1, CC * LL, CC * LL, CC * LL, H1, 0, 0, 0, 0, 0);

    // 8) fc2: out = h @ W2^T + b2
    tf_gemm<2><<<dim3(OUTN / 128, BATCH / 128, 1), 256, TF32_SMEM>>>(
        h, W2, b2, nullptr, nullptr, out,
        BATCH, OUTN, H1, H1, H1, OUTN, 0, 0, 0, 0, 0);
}

// round 11
// speedup vs baseline: 4.0585x; 1.2884x over previous
#include <cuda_runtime.h>
#include <cuda_bf16.h>
#include <cstdint>

// Problem dims
#define BATCH 256
#define CIN   2048
#define LL    150
#define LP    152      // padded L stride (16B-aligned rows for cp.async)
#define CC    256
#define H1    8192
#define OUTN  2048

// Scratch (device globals; no dynamic allocation allowed)
__device__ __align__(16) float g_pvT[BATCH * LL * CC];    // [B][L][C] tf32-rounded
__device__ __align__(16) float g_pv [BATCH * CC * LP];    // [B][C][LP] tf32-rounded
__device__ __align__(16) float g_qT [BATCH * LL * CC];    // [B][L][C] tf32-rounded
__device__ __align__(16) float g_kT [BATCH * LL * CC];    // [B][L][C]
__device__ __align__(16) float g_att[BATCH * LL * LP];    // [B][L][LP]
__device__ __align__(16) float g_out[BATCH * CC * LL];    // [B][C][L] packed, rounded
__device__ __align__(16) float g_h  [BATCH * H1];         // tf32-rounded
__device__ __align__(16) float g_xT [BATCH * LL * CIN];   // [B][L][CIN] rounded
__device__ __align__(16) float g_prt[8 * BATCH * OUTN > 2 * BATCH * H1
                                     ? 8 * BATCH * OUTN : 2 * BATCH * H1]; // split-K partials

// ===========================================================================
// tf32 warp MMA + cp.async helpers (family-portable PTX, plain sm_103 OK)
// ===========================================================================
__device__ __forceinline__ void mma_tf32(float* c, const uint32_t* a,
                                         const uint32_t* b) {
    asm volatile(
        "mma.sync.aligned.m16n8k8.row.col.f32.tf32.tf32.f32 "
        "{%0,%1,%2,%3}, {%4,%5,%6,%7}, {%8,%9}, {%0,%1,%2,%3};"
        : "+f"(c[0]), "+f"(c[1]), "+f"(c[2]), "+f"(c[3])
        : "r"(a[0]), "r"(a[1]), "r"(a[2]), "r"(a[3]), "r"(b[0]), "r"(b[1]));
}
__device__ __forceinline__ uint32_t f2tf32(float x) {
    uint32_t o;
    asm("cvt.rna.tf32.f32 %0, %1;" : "=r"(o) : "f"(x));
    return o;
}
__device__ __forceinline__ float roundtf(float x) {
    return __uint_as_float(f2tf32(x));
}
__device__ __forceinline__ uint32_t smem_u32(const void* p) {
    uint32_t a;
    asm("{ .reg .u64 t; cvta.to.shared.u64 t, %1; cvt.u32.u64 %0, t; }"
        : "=r"(a) : "l"(p));
    return a;
}
#define CP_COMMIT() asm volatile("cp.async.commit_group;" ::: "memory")

// ===========================================================================
// Single-pass tf32 GEMM, cp.async 2-stage pipeline, 2 CTAs/SM.
// C[M,N] = A[M,K] * B[N,K]^T (+ epilogue).
// A MUST be pre-rounded to tf32 grid (af used raw); B cvt'd in registers.
// Tile 128x128, BK=32, 256 threads (8 warps, 64x32/warp).
// EPI: 0 none, 1 +bias[m], 2 +bias[n], 3 gamma[0]*acc + res[]
// RND: 1 -> round stored C to tf32 grid (for outputs feeding GEMM-A inputs)
// ===========================================================================
#define RSF    36
#define TILEF  (128 * RSF)
#define TILE_BY (TILEF * 4)
#define STAGE_BY (2 * TILE_BY)
#define TF32_SMEM (2 * STAGE_BY)     // 73728 bytes

__device__ __forceinline__ void cp_tile(const float* __restrict__ G, int rows,
        int Kdim, int ld, int row0, int k0, uint32_t dstBase, int tid)
{
    const int r  = tid >> 1;
    const int cb = (tid & 1) * 16;
    const int gr = row0 + r;
    const bool rok = gr < rows;
    const float* Grow = G + (long long)(rok ? gr : 0) * ld;
    const uint32_t drow = dstBase + (uint32_t)(r * RSF + cb) * 4u;
#pragma unroll
    for (int i = 0; i < 4; i++) {
        int gk = k0 + cb + i * 4;
        int rem = Kdim - gk;
        int sz = rok ? (rem >= 4 ? 16 : (rem > 0 ? rem * 4 : 0)) : 0;
        const float* src = (sz > 0) ? (Grow + gk) : G;
        asm volatile("cp.async.cg.shared.global [%0], [%1], 16, %2;"
                     :: "r"(drow + (uint32_t)i * 16u), "l"(src), "r"(sz));
    }
}

template<int EPI, int RND>
__global__ __launch_bounds__(256, 2)
void tf_gemm(const float* __restrict__ A, const float* __restrict__ B,
             const float* __restrict__ bias, const float* __restrict__ gamma,
             const float* __restrict__ res, float* __restrict__ C,
             int M, int N, int K, int lda, int ldb, int ldc, int ldr,
             long long sA, long long sB, long long sC, long long sR)
{
    extern __shared__ __align__(16) float sm[];

    A += (long long)blockIdx.z * sA;
    B += (long long)blockIdx.z * sB;
    C += (long long)blockIdx.z * sC;
    if (EPI == 3) res += (long long)blockIdx.z * sR;

    const int tid  = threadIdx.x;
    const int wid  = tid >> 5;
    const int lane = tid & 31;
    const int wm = wid >> 2;
    const int wn = wid & 3;
    const int m0 = blockIdx.y * 128;
    const int n0 = blockIdx.x * 128;

    const uint32_t smb = smem_u32(sm);
    const int ag = lane >> 2;
    const int ac = lane & 3;

    float acc[4][4][4];
#pragma unroll
    for (int mi = 0; mi < 4; mi++)
#pragma unroll
        for (int ni = 0; ni < 4; ni++)
#pragma unroll
            for (int v = 0; v < 4; v++) acc[mi][ni][v] = 0.f;

    const int nch = (K + 31) >> 5;

    cp_tile(A, M, K, lda, m0, 0, smb,           tid);
    cp_tile(B, N, K, ldb, n0, 0, smb + TILE_BY, tid);
    CP_COMMIT();

    for (int ch = 0; ch < nch; ch++) {
        const int nxt = ch + 1;
        if (nxt < nch) {
            const uint32_t st = smb + (uint32_t)(nxt & 1) * STAGE_BY;
            cp_tile(A, M, K, lda, m0, nxt * 32, st,           tid);
            cp_tile(B, N, K, ldb, n0, nxt * 32, st + TILE_BY, tid);
            CP_COMMIT();
            asm volatile("cp.async.wait_group 1;" ::: "memory");
        } else {
            asm volatile("cp.async.wait_group 0;" ::: "memory");
        }
        __syncthreads();

        const float* SA = sm + (ch & 1) * (STAGE_BY / 4);
        const uint32_t* UA = reinterpret_cast<const uint32_t*>(SA);
        const float* SB = SA + TILEF;

#pragma unroll
        for (int ks = 0; ks < 4; ks++) {
            const int kc = ks * 8 + ac;
            uint32_t af[4][4];
#pragma unroll
            for (int mi = 0; mi < 4; mi++) {
                int rr = wm * 64 + mi * 16 + ag;
                af[mi][0] = UA[rr * RSF + kc];          // A pre-rounded: raw bits
                af[mi][1] = UA[(rr + 8) * RSF + kc];
                af[mi][2] = UA[rr * RSF + kc + 4];
                af[mi][3] = UA[(rr + 8) * RSF + kc + 4];
            }
            uint32_t bf[4][2];
#pragma unroll
            for (int ni = 0; ni < 4; ni++) {
                int nn = wn * 32 + ni * 8 + ag;
                bf[ni][0] = f2tf32(SB[nn * RSF + kc]);
                bf[ni][1] = f2tf32(SB[nn * RSF + kc + 4]);
            }
#pragma unroll
            for (int mi = 0; mi < 4; mi++)
#pragma unroll
                for (int ni = 0; ni < 4; ni++)
                    mma_tf32(acc[mi][ni], af[mi], bf[ni]);
        }
        __syncthreads();
    }

    const float gm_s = (EPI == 3) ? gamma[0] : 0.f;
#pragma unroll
    for (int mi = 0; mi < 4; mi++) {
        int gm0 = m0 + wm * 64 + mi * 16 + ag;
#pragma unroll
        for (int half = 0; half < 2; half++) {
            int gm = gm0 + half * 8;
            if (gm >= M) continue;
            float bm = (EPI == 1) ? bias[gm] : 0.f;
#pragma unroll
            for (int ni = 0; ni < 4; ni++) {
                int gn = n0 + wn * 32 + ni * 8 + 2 * ac;
                if (gn >= N) continue;
                float v0 = acc[mi][ni][half * 2];
                float v1 = acc[mi][ni][half * 2 + 1];
                long long idx = (long long)gm * ldc + gn;
                if (EPI == 1) { v0 += bm; v1 += bm; }
                if (EPI == 2) { v0 += bias[gn]; v1 += (gn + 1 < N) ? bias[gn + 1] : 0.f; }
                if (EPI == 3) {
                    long long ridx = (long long)gm * ldr + gn;
                    v0 = gm_s * v0 + res[ridx];
                    if (gn + 1 < N) v1 = gm_s * v1 + res[ridx + 1];
                }
                if (RND) { v0 = roundtf(v0); v1 = roundtf(v1); }
                if (gn + 1 < N) {
                    *reinterpret_cast<float2*>(C + idx) = make_float2(v0, v1);
                } else {
                    C[idx] = v0;
                }
            }
        }
    }
}

// ===========================================================================
// Split-K reduction: out[i] = round?( sum_s part[s*MN+i] + bias[i%N] )
// ===========================================================================
template<int S, int RND>
__global__ void reduce_bias_kernel(const float* __restrict__ part,
                                   const float* __restrict__ bias,
                                   float* __restrict__ out, int MN, int N)
{
    int i4 = (blockIdx.x * blockDim.x + threadIdx.x) * 4;
    if (i4 >= MN) return;
    float4 s = *reinterpret_cast<const float4*>(part + i4);
#pragma unroll
    for (int k = 1; k < S; k++) {
        float4 p = *reinterpret_cast<const float4*>(part + (long long)k * MN + i4);
        s.x += p.x; s.y += p.y; s.z += p.z; s.w += p.w;
    }
    int n = i4 % N;
    const float4 b = *reinterpret_cast<const float4*>(bias + n);
    s.x += b.x; s.y += b.y; s.z += b.z; s.w += b.w;
    if (RND) {
        s.x = roundtf(s.x); s.y = roundtf(s.y);
        s.z = roundtf(s.z); s.w = roundtf(s.w);
    }
    *reinterpret_cast<float4*>(out + i4) = s;
}

// ===========================================================================
// x transpose: [B][CIN][L] -> [B][L][CIN], tf32-rounded (feeds pv GEMM A)
// ===========================================================================
__global__ void transpose_x_kernel(const float* __restrict__ x, float* __restrict__ xT)
{
    __shared__ float t[32][33];
    int b  = blockIdx.z;
    int c0 = blockIdx.y * 32, l0 = blockIdx.x * 32;
    const float* xb = x + (long long)b * CIN * LL;
    float* xTb = xT + (long long)b * LL * CIN;
    int tx = threadIdx.x, ty = threadIdx.y;
#pragma unroll
    for (int i = ty; i < 32; i += 8) {
        int c = c0 + i, l = l0 + tx;
        t[i][tx] = (c < CIN && l < LL) ? xb[(long long)c * LL + l] : 0.f;
    }
    __syncthreads();
#pragma unroll
    for (int i = ty; i < 32; i += 8) {
        int l = l0 + i, c = c0 + tx;
        if (l < LL && c < CIN) xTb[(long long)l * CIN + c] = roundtf(t[tx][i]);
    }
}

// pvT [B][L][C] (already rounded) -> pv [B][C][LP]
__global__ void transpose_pv_kernel(const float* __restrict__ in, float* __restrict__ out)
{
    __shared__ float t[32][33];
    int b  = blockIdx.z;
    int c0 = blockIdx.x * 32, l0 = blockIdx.y * 32;
    const float* ib = in + (long long)b * LL * CC;
    float* ob = out + (long long)b * CC * LP;
    int tx = threadIdx.x, ty = threadIdx.y;
#pragma unroll
    for (int i = ty; i < 32; i += 8) {
        int l = l0 + i;
        if (l < LL) t[i][tx] = ib[(long long)l * CC + c0 + tx];
    }
    __syncthreads();
#pragma unroll
    for (int i = ty; i < 32; i += 8) {
        int l = l0 + tx;
        if (l < LL) ob[(long long)(c0 + i) * LP + l] = t[tx][i];
    }
}

// ---------------------------------------------------------------------------
__global__ void softmax_rows_kernel(float* __restrict__ att, int rows)
{
    int warp = (blockIdx.x * blockDim.x + threadIdx.x) >> 5;
    int lane = threadIdx.x & 31;
    if (warp >= rows) return;
    float* row = att + (long long)warp * LP;

    float vals[5];
    float mx = -1e30f;
#pragma unroll
    for (int i = 0; i < 5; i++) {
        int c = lane + 32 * i;
        vals[i] = (c < LL) ? row[c] : -1e30f;
        mx = fmaxf(mx, vals[i]);
    }
#pragma unroll
    for (int o = 16; o; o >>= 1) mx = fmaxf(mx, __shfl_xor_sync(0xffffffffu, mx, o));

    float s = 0.f;
#pragma unroll
    for (int i = 0; i < 5; i++) {
        vals[i] = expf(vals[i] - mx);
        s += vals[i];
    }
#pragma unroll
    for (int o = 16; o; o >>= 1) s += __shfl_xor_sync(0xffffffffu, s, o);
    float inv = 1.f / s;
#pragma unroll
    for (int i = 0; i < 5; i++) {
        int c = lane + 32 * i;
        if (c < LL) row[c] = vals[i] * inv;
    }
}

static inline int ceil_div(int a, int b) { return (a + b - 1) / b; }

extern "C" void kernel_launch(void* const* d_in, const int* in_sizes, int n_in,
                              void* d_out, int out_size)
{
    const float* x     = (const float*)d_in[0];
    const float* Wv    = (const float*)d_in[1];
    const float* bv    = (const float*)d_in[2];
    const float* Wq    = (const float*)d_in[3];
    const float* bq    = (const float*)d_in[4];
    const float* Wk    = (const float*)d_in[5];
    const float* bk    = (const float*)d_in[6];
    const float* gamma = (const float*)d_in[7];
    const float* W1    = (const float*)d_in[8];
    const float* b1    = (const float*)d_in[9];
    const float* W2    = (const float*)d_in[10];
    const float* b2    = (const float*)d_in[11];
    float* out = (float*)d_out;

    float *pvT, *pv, *qT, *kT, *att, *aout, *h, *xT, *prt;
    cudaGetSymbolAddress((void**)&pvT, g_pvT);
    cudaGetSymbolAddress((void**)&pv,  g_pv);
    cudaGetSymbolAddress((void**)&qT,  g_qT);
    cudaGetSymbolAddress((void**)&kT,  g_kT);
    cudaGetSymbolAddress((void**)&att, g_att);
    cudaGetSymbolAddress((void**)&aout,g_out);
    cudaGetSymbolAddress((void**)&h,   g_h);
    cudaGetSymbolAddress((void**)&xT,  g_xT);
    cudaGetSymbolAddress((void**)&prt, g_prt);

    static bool attr_done = false;
    if (!attr_done) {
        cudaFuncSetAttribute(tf_gemm<0,0>, cudaFuncAttributeMaxDynamicSharedMemorySize, TF32_SMEM);
        cudaFuncSetAttribute(tf_gemm<2,1>, cudaFuncAttributeMaxDynamicSharedMemorySize, TF32_SMEM);
        cudaFuncSetAttribute(tf_gemm<3,1>, cudaFuncAttributeMaxDynamicSharedMemorySize, TF32_SMEM);
        attr_done = true;
    }

    const long long sPVT = (long long)LL * CC;   // 38400
    const long long sPVp = (long long)CC * LP;   // 38912
    const long long sATp = (long long)LL * LP;   // 22800
    const long long sXT  = (long long)LL * CIN;  // 307200
    const long long sAO  = (long long)CC * LL;   // 38400 (packed)

    // 0) transpose x -> xT (tf32-rounded)
    transpose_x_kernel<<<dim3(ceil_div(LL, 32), CIN / 32, BATCH), dim3(32, 8)>>>(x, xT);

    // 1) pvT[b][L,C] = xT[b] @ Wv^T + bv[n]  (rounded output)
    tf_gemm<2,1><<<dim3(CC / 128, ceil_div(LL, 128), BATCH), 256, TF32_SMEM>>>(
        xT, Wv, bv, nullptr, nullptr, pvT,
        LL, CC, CIN, CIN, CIN, CC, 0, sXT, 0, sPVT, 0);

    // 2) pv[b][C,LP] = pvT^T (already rounded)
    transpose_pv_kernel<<<dim3(CC / 32, ceil_div(LL, 32), BATCH), dim3(32, 8)>>>(pvT, pv);

    // 3) qT, kT  (rounded outputs)
    {
        dim3 grid(CC / 128, ceil_div(LL, 128), BATCH);
        tf_gemm<2,1><<<grid, 256, TF32_SMEM>>>(pvT, Wq, bq, nullptr, nullptr, qT,
            LL, CC, CC, CC, CC, CC, 0, sPVT, 0, sPVT, 0);
        tf_gemm<2,1><<<grid, 256, TF32_SMEM>>>(pvT, Wk, bk, nullptr, nullptr, kT,
            LL, CC, CC, CC, CC, CC, 0, sPVT, 0, sPVT, 0);
    }
    // 4) energy[b][L,LP] = qT @ kT^T
    tf_gemm<0,0><<<dim3(ceil_div(LL, 128), ceil_div(LL, 128), BATCH), 256, TF32_SMEM>>>(
        qT, kT, nullptr, nullptr, nullptr, att,
        LL, LL, CC, CC, CC, LP, 0, sPVT, sPVT, sATp, 0);

    // 5) softmax rows
    {
        int rows = BATCH * LL;
        int blocks = ceil_div(rows * 32, 256);
        softmax_rows_kernel<<<blocks, 256>>>(att, rows);
    }
    // 6) aout[b][C,L] = gamma * (pv @ att^T) + pv   (rounded, packed for fc1)
    tf_gemm<3,1><<<dim3(ceil_div(LL, 128), CC / 128, BATCH), 256, TF32_SMEM>>>(
        pv, att, nullptr, gamma, pv, aout,
        CC, LL, LL, LP, LP, LL, LP, sPVp, sATp, sAO, sPVp);

    // 7) fc1 split-K x2: partials, then reduce+bias (rounds h)
    {
        const int KS = CC * LL / 2;              // 19200
        tf_gemm<0,0><<<dim3(H1 / 128, BATCH / 128, 2), 256, TF32_SMEM>>>(
            aout, W1, nullptr, nullptr, nullptr, prt,
            BATCH, H1, KS, CC * LL, CC * LL, H1, 0,
            KS, KS, (long long)BATCH * H1, 0);
        int mn = BATCH * H1;
        reduce_bias_kernel<2,1><<<ceil_div(mn / 4, 256), 256>>>(prt, b1, h, mn, H1);
    }
    // 8) fc2 split-K x8: partials, then reduce+bias (final output, no round)
    {
        const int KS = H1 / 8;                   // 1024
        tf_gemm<0,0><<<dim3(OUTN / 128, BATCH / 128, 8), 256, TF32_SMEM>>>(
            h, W2, nullptr, nullptr, nullptr, prt,
            BATCH, OUTN, KS, H1, H1, OUTN, 0,
            KS, KS, (long long)BATCH * OUTN, 0);
        int mn = BATCH * OUTN;
        reduce_bias_kernel<8,0><<<ceil_div(mn / 4, 256), 256>>>(prt, b2, out, mn, OUTN);
    }
}